// round 1
// baseline (speedup 1.0000x reference)
#include <cuda_runtime.h>

// Problem constants
#define NN   20000          // nodes
#define BB   16             // batch
#define FF   64             // feat
#define CC   1024           // B*F columns of x
#define C4   256            // CC/4 (float4 per row)
#define EE   640000         // edges
#define ODIM 64             // output dim
#define KDIM 192            // F*M

#define AS_STRIDE 193       // [nl][k] stride, odd -> conflict-free a-broadcast
#define GEMM_SMEM ((64*AS_STRIDE + KDIM*ODIM) * 4)

// Scratch (allocation-free rule: __device__ globals)
__device__ float g_x0[NN * CC];
__device__ float g_x1[NN * CC];
__device__ float g_x2[NN * CC];
__device__ int   g_rp[NN + 1];

// ---------------------------------------------------------------------------
// 1) Pack inputs [B,N,F] -> x0 [N, B*F]  (col = b*F + f)
// ---------------------------------------------------------------------------
__global__ void pack_kernel(const float4* __restrict__ in4) {
    int g  = blockIdx.x * 256 + threadIdx.x;   // 0 .. NN*C4-1 (grid sized exactly)
    int f4 = g & 15;
    int b  = (g >> 4) & 15;
    int n  = g >> 8;
    ((float4*)g_x0)[g] = in4[(b * NN + n) * 16 + f4];
}

// ---------------------------------------------------------------------------
// 2) Row pointers from sorted rows
// ---------------------------------------------------------------------------
__global__ void rowptr_kernel(const int* __restrict__ rows) {
    int i = blockIdx.x * 256 + threadIdx.x;
    if (i >= EE) return;
    int r    = rows[i];
    int prev = (i == 0) ? -1 : rows[i - 1];
    for (int rr = prev + 1; rr <= r; rr++) g_rp[rr] = i;
    if (i == EE - 1) {
        for (int rr = r + 1; rr <= NN; rr++) g_rp[rr] = EE;
    }
}

// ---------------------------------------------------------------------------
// 3) SpMM: one block (256 threads) per row; each thread owns 1 float4 column
//    PHASE 1: x1 = A @ x0
//    PHASE 2: x2 = 2 * (A @ x1) - x0
// ---------------------------------------------------------------------------
template <int PHASE>
__global__ void __launch_bounds__(256) spmm_kernel(const int* __restrict__ cols,
                                                   const float* __restrict__ vals) {
    const float4* __restrict__ x = (const float4*)(PHASE == 1 ? g_x0 : g_x1);
    float4* __restrict__ y       = (float4*)(PHASE == 1 ? g_x1 : g_x2);

    int n = blockIdx.x;
    int t = threadIdx.x;
    int s = g_rp[n];
    int e = g_rp[n + 1];

    __shared__ int   sc[256];
    __shared__ float sv[256];

    float4 acc = make_float4(0.f, 0.f, 0.f, 0.f);

    for (int base = s; base < e; base += 256) {
        int cnt = min(256, e - base);
        __syncthreads();
        if (t < cnt) {
            sc[t] = cols[base + t];
            sv[t] = vals[base + t];
        }
        __syncthreads();
        #pragma unroll 4
        for (int j = 0; j < cnt; j++) {
            float  v  = sv[j];
            float4 xv = x[sc[j] * C4 + t];
            acc.x += v * xv.x;
            acc.y += v * xv.y;
            acc.z += v * xv.z;
            acc.w += v * xv.w;
        }
    }

    if (PHASE == 2) {
        float4 x0v = ((const float4*)g_x0)[n * C4 + t];
        acc.x = 2.f * acc.x - x0v.x;
        acc.y = 2.f * acc.y - x0v.y;
        acc.z = 2.f * acc.z - x0v.z;
        acc.w = 2.f * acc.w - x0v.w;
    }
    y[n * C4 + t] = acc;
}

// ---------------------------------------------------------------------------
// 4) GEMM: out[(b*N+n), o] = bias[o] + sum_{f,m} xs[m][n, b*F+f] * W[f*3+m, o]
//    Tile: 64 rows (n) x 64 cols (o), k = 192 (reordered k = m*64+f).
//    Block 128 threads, 4x8 micro-tile. W permuted into shared once per block.
// ---------------------------------------------------------------------------
__device__ __forceinline__ void stage_a(const float* __restrict__ src, int mbase,
                                        float* __restrict__ As, int n0, int b, int t) {
    for (int idx = t; idx < 64 * 16; idx += 128) {
        int nl = idx >> 4;
        int f4 = idx & 15;
        int n  = n0 + nl;
        float4 v = make_float4(0.f, 0.f, 0.f, 0.f);
        if (n < NN) v = ((const float4*)src)[n * C4 + b * 16 + f4];
        float* p = As + nl * AS_STRIDE + mbase + f4 * 4;
        p[0] = v.x; p[1] = v.y; p[2] = v.z; p[3] = v.w;
    }
}

__global__ void __launch_bounds__(128) gemm_kernel(const float* __restrict__ weight,
                                                   const float* __restrict__ bias,
                                                   float* __restrict__ out) {
    extern __shared__ float sh[];
    float* As = sh;                       // [64][AS_STRIDE], index nl*193 + (m*64+f)
    float* Ws = sh + 64 * AS_STRIDE;      // [192][64], row k = m*64+f

    int t  = threadIdx.x;                 // 128 threads
    int n0 = blockIdx.x * 64;
    int b  = blockIdx.y;

    // Stage W with the (f*3+m) -> (m*64+f) row permutation
    for (int idx = t; idx < KDIM * 16; idx += 128) {
        int krow = idx >> 4;
        int o4   = idx & 15;
        int f    = krow & 63;
        int m    = krow >> 6;
        float4 w = ((const float4*)weight)[(f * 3 + m) * 16 + o4];
        *(float4*)(Ws + krow * ODIM + o4 * 4) = w;
    }

    stage_a(g_x0, 0,   As, n0, b, t);
    stage_a(g_x1, 64,  As, n0, b, t);
    stage_a(g_x2, 128, As, n0, b, t);
    __syncthreads();

    int tx = t & 7;                       // o0 = tx*8
    int ty = t >> 3;                      // r0 = ty*4  (ty in 0..15)
    int o0 = tx * 8;
    int r0 = ty * 4;

    float acc[4][8];
    #pragma unroll
    for (int i = 0; i < 4; i++)
        #pragma unroll
        for (int j = 0; j < 8; j++) acc[i][j] = 0.f;

    #pragma unroll 2
    for (int k = 0; k < KDIM; k++) {
        const float* wr = Ws + k * ODIM + o0;
        float4 w0 = *(const float4*)(wr);
        float4 w1 = *(const float4*)(wr + 4);
        float a[4];
        #pragma unroll
        for (int i = 0; i < 4; i++) a[i] = As[(r0 + i) * AS_STRIDE + k];
        #pragma unroll
        for (int i = 0; i < 4; i++) {
            acc[i][0] += a[i] * w0.x;
            acc[i][1] += a[i] * w0.y;
            acc[i][2] += a[i] * w0.z;
            acc[i][3] += a[i] * w0.w;
            acc[i][4] += a[i] * w1.x;
            acc[i][5] += a[i] * w1.y;
            acc[i][6] += a[i] * w1.z;
            acc[i][7] += a[i] * w1.w;
        }
    }

    float4 bv0 = ((const float4*)bias)[tx * 2];
    float4 bv1 = ((const float4*)bias)[tx * 2 + 1];

    #pragma unroll
    for (int i = 0; i < 4; i++) {
        int n = n0 + r0 + i;
        if (n < NN) {
            long long row = (long long)b * NN + n;
            float* op = out + row * ODIM + o0;
            float4 r0v = make_float4(acc[i][0] + bv0.x, acc[i][1] + bv0.y,
                                     acc[i][2] + bv0.z, acc[i][3] + bv0.w);
            float4 r1v = make_float4(acc[i][4] + bv1.x, acc[i][5] + bv1.y,
                                     acc[i][6] + bv1.z, acc[i][7] + bv1.w);
            *(float4*)(op)     = r0v;
            *(float4*)(op + 4) = r1v;
        }
    }
}

// ---------------------------------------------------------------------------
// Launch
// ---------------------------------------------------------------------------
extern "C" void kernel_launch(void* const* d_in, const int* in_sizes, int n_in,
                              void* d_out, int out_size) {
    const float4* inputs = (const float4*)d_in[0];
    const int*    rows   = (const int*)d_in[1];
    const int*    cols   = (const int*)d_in[2];
    const float*  vals   = (const float*)d_in[3];
    const float*  weight = (const float*)d_in[4];
    const float*  bias   = (const float*)d_in[5];
    float*        out    = (float*)d_out;

    cudaFuncSetAttribute(gemm_kernel, cudaFuncAttributeMaxDynamicSharedMemorySize,
                         GEMM_SMEM);

    pack_kernel<<<NN, 256>>>(inputs);                         // exact: NN*C4/256 = NN
    rowptr_kernel<<<(EE + 255) / 256, 256>>>(rows);
    spmm_kernel<1><<<NN, 256>>>(cols, vals);
    spmm_kernel<2><<<NN, 256>>>(cols, vals);
    gemm_kernel<<<dim3((NN + 63) / 64, BB), 128, GEMM_SMEM>>>(weight, bias, out);
}

// round 2
// speedup vs baseline: 1.4439x; 1.4439x over previous
#include <cuda_runtime.h>

// Problem constants
#define NN   20000          // nodes
#define BB   16             // batch
#define FF   64             // feat
#define CC   1024           // B*F columns of x
#define C4   256            // CC/4 (float4 per row)
#define EE   640000         // edges
#define ODIM 64             // output dim
#define KDIM 192            // F*M

#define AS_STRIDE 193       // [nl][k] stride, odd -> conflict-free a-broadcast
#define GEMM_SMEM ((64*AS_STRIDE + KDIM*ODIM) * 4)

typedef unsigned long long u64;

// Scratch (allocation-free rule: __device__ globals)
__device__ float g_x0[NN * CC];
__device__ float g_x1[NN * CC];
__device__ float g_x2[NN * CC];
__device__ int   g_rp[NN + 1];

// ---------------------------------------------------------------------------
// f32x2 packed-math helpers (FFMA2 — only reachable via PTX)
// ---------------------------------------------------------------------------
__device__ __forceinline__ u64 pack2(float lo, float hi) {
    u64 r; asm("mov.b64 %0, {%1, %2};" : "=l"(r) : "f"(lo), "f"(hi)); return r;
}
__device__ __forceinline__ void unpack2(u64 v, float& lo, float& hi) {
    asm("mov.b64 {%0, %1}, %2;" : "=f"(lo), "=f"(hi) : "l"(v));
}
__device__ __forceinline__ u64 fma2(u64 a, u64 b, u64 c) {
    u64 d; asm("fma.rn.f32x2 %0, %1, %2, %3;" : "=l"(d) : "l"(a), "l"(b), "l"(c));
    return d;
}

// ---------------------------------------------------------------------------
// 1) Pack inputs [B,N,F] -> x0 [N, B*F]  (col = b*F + f)
// ---------------------------------------------------------------------------
__global__ void pack_kernel(const float4* __restrict__ in4) {
    int g  = blockIdx.x * 256 + threadIdx.x;   // grid sized exactly NN*C4/256
    int f4 = g & 15;
    int b  = (g >> 4) & 15;
    int n  = g >> 8;
    ((float4*)g_x0)[g] = in4[(b * NN + n) * 16 + f4];
}

// ---------------------------------------------------------------------------
// 2) Row pointers from sorted rows
// ---------------------------------------------------------------------------
__global__ void rowptr_kernel(const int* __restrict__ rows) {
    int i = blockIdx.x * 256 + threadIdx.x;
    if (i >= EE) return;
    int r    = rows[i];
    int prev = (i == 0) ? -1 : rows[i - 1];
    for (int rr = prev + 1; rr <= r; rr++) g_rp[rr] = i;
    if (i == EE - 1) {
        for (int rr = r + 1; rr <= NN; rr++) g_rp[rr] = EE;
    }
}

// ---------------------------------------------------------------------------
// 3) SpMM: grid (NN, 2) — blockIdx.y picks a column half (512 cols = 41MB,
//    keeps the per-pass working set L2-resident). 128 threads, 1 float4 each.
//    Edge (col,val) broadcast staged in smem, consumed as int4/float4.
//    PHASE 1: x1 = A @ x0        PHASE 2: x2 = 2*(A @ x1) - x0
// ---------------------------------------------------------------------------
template <int PHASE>
__global__ void __launch_bounds__(128) spmm_kernel(const int* __restrict__ cols,
                                                   const float* __restrict__ vals) {
    const float4* __restrict__ x = (const float4*)(PHASE == 1 ? g_x0 : g_x1);
    float4* __restrict__ y       = (float4*)(PHASE == 1 ? g_x1 : g_x2);

    int n = blockIdx.x;
    int t = threadIdx.x;
    int c = blockIdx.y * 128 + t;          // float4 column index (0..255)
    int s = g_rp[n];
    int e = g_rp[n + 1];

    __shared__ int   sc[128];
    __shared__ float sv[128];

    float4 acc = make_float4(0.f, 0.f, 0.f, 0.f);

    for (int base = s; base < e; base += 128) {
        int cnt = min(128, e - base);
        __syncthreads();
        if (t < cnt) {
            sc[t] = cols[base + t];
            sv[t] = vals[base + t];
        }
        __syncthreads();

        int j = 0;
        for (; j + 4 <= cnt; j += 4) {
            int4   c4 = *(const int4*)&sc[j];
            float4 v4 = *(const float4*)&sv[j];
            float4 x0v = x[c4.x * C4 + c];
            float4 x1v = x[c4.y * C4 + c];
            float4 x2v = x[c4.z * C4 + c];
            float4 x3v = x[c4.w * C4 + c];
            acc.x += v4.x * x0v.x; acc.y += v4.x * x0v.y;
            acc.z += v4.x * x0v.z; acc.w += v4.x * x0v.w;
            acc.x += v4.y * x1v.x; acc.y += v4.y * x1v.y;
            acc.z += v4.y * x1v.z; acc.w += v4.y * x1v.w;
            acc.x += v4.z * x2v.x; acc.y += v4.z * x2v.y;
            acc.z += v4.z * x2v.z; acc.w += v4.z * x2v.w;
            acc.x += v4.w * x3v.x; acc.y += v4.w * x3v.y;
            acc.z += v4.w * x3v.z; acc.w += v4.w * x3v.w;
        }
        for (; j < cnt; j++) {
            float  v  = sv[j];
            float4 xv = x[sc[j] * C4 + c];
            acc.x += v * xv.x; acc.y += v * xv.y;
            acc.z += v * xv.z; acc.w += v * xv.w;
        }
    }

    if (PHASE == 2) {
        float4 x0v = ((const float4*)g_x0)[n * C4 + c];
        acc.x = 2.f * acc.x - x0v.x;
        acc.y = 2.f * acc.y - x0v.y;
        acc.z = 2.f * acc.z - x0v.z;
        acc.w = 2.f * acc.w - x0v.w;
    }
    y[n * C4 + c] = acc;
}

// ---------------------------------------------------------------------------
// 4) GEMM: out[(b*N+n), o] = bias[o] + sum_{f,m} xs[m][n, b*F+f] * W[f*3+m, o]
//    64 rows x 64 cols per block, 128 threads, 4x8 micro-tile computed as
//    4x4 f32x2 pairs via fma.rn.f32x2 (FFMA2).
// ---------------------------------------------------------------------------
__device__ __forceinline__ void stage_a(const float* __restrict__ src, int mbase,
                                        float* __restrict__ As, int n0, int b, int t) {
    for (int idx = t; idx < 64 * 16; idx += 128) {
        int nl = idx >> 4;
        int f4 = idx & 15;
        int n  = n0 + nl;
        float4 v = make_float4(0.f, 0.f, 0.f, 0.f);
        if (n < NN) v = ((const float4*)src)[n * C4 + b * 16 + f4];
        float* p = As + nl * AS_STRIDE + mbase + f4 * 4;
        p[0] = v.x; p[1] = v.y; p[2] = v.z; p[3] = v.w;
    }
}

__global__ void __launch_bounds__(128) gemm_kernel(const float* __restrict__ weight,
                                                   const float* __restrict__ bias,
                                                   float* __restrict__ out) {
    extern __shared__ float sh[];
    float* As = sh;                       // [64][AS_STRIDE], index nl*193 + (m*64+f)
    float* Ws = sh + 64 * AS_STRIDE;      // [192][64], row k = m*64+f (16B aligned)

    int t  = threadIdx.x;                 // 128 threads
    int n0 = blockIdx.x * 64;
    int b  = blockIdx.y;

    // Stage W with the (f*3+m) -> (m*64+f) row permutation
    for (int idx = t; idx < KDIM * 16; idx += 128) {
        int krow = idx >> 4;
        int o4   = idx & 15;
        int f    = krow & 63;
        int m    = krow >> 6;
        float4 w = ((const float4*)weight)[(f * 3 + m) * 16 + o4];
        *(float4*)(Ws + krow * ODIM + o4 * 4) = w;
    }

    stage_a(g_x0, 0,   As, n0, b, t);
    stage_a(g_x1, 64,  As, n0, b, t);
    stage_a(g_x2, 128, As, n0, b, t);
    __syncthreads();

    int tx = t & 7;                       // o0 = tx*8
    int ty = t >> 3;                      // r0 = ty*4  (ty in 0..15)
    int o0 = tx * 8;
    int r0 = ty * 4;

    u64 acc2[4][4];
    #pragma unroll
    for (int i = 0; i < 4; i++)
        #pragma unroll
        for (int j = 0; j < 4; j++) acc2[i][j] = 0ULL;

    const float* arow = As + r0 * AS_STRIDE;

    #pragma unroll 8
    for (int k = 0; k < KDIM; k++) {
        // 8 w-values = 4 f32x2 pairs, two 16B shared loads
        const ulonglong2* wr = (const ulonglong2*)(Ws + k * ODIM + o0);
        ulonglong2 w01 = wr[0];
        ulonglong2 w23 = wr[1];

        u64 ad[4];
        #pragma unroll
        for (int i = 0; i < 4; i++) {
            float a = arow[i * AS_STRIDE + k];
            ad[i] = pack2(a, a);
        }
        #pragma unroll
        for (int i = 0; i < 4; i++) {
            acc2[i][0] = fma2(ad[i], w01.x, acc2[i][0]);
            acc2[i][1] = fma2(ad[i], w01.y, acc2[i][1]);
            acc2[i][2] = fma2(ad[i], w23.x, acc2[i][2]);
            acc2[i][3] = fma2(ad[i], w23.y, acc2[i][3]);
        }
    }

    float bo[8];
    #pragma unroll
    for (int j = 0; j < 8; j++) bo[j] = bias[o0 + j];

    #pragma unroll
    for (int i = 0; i < 4; i++) {
        int n = n0 + r0 + i;
        if (n < NN) {
            long long row = (long long)b * NN + n;
            float* op = out + row * ODIM + o0;
            float r[8];
            unpack2(acc2[i][0], r[0], r[1]);
            unpack2(acc2[i][1], r[2], r[3]);
            unpack2(acc2[i][2], r[4], r[5]);
            unpack2(acc2[i][3], r[6], r[7]);
            float4 v0 = make_float4(r[0] + bo[0], r[1] + bo[1], r[2] + bo[2], r[3] + bo[3]);
            float4 v1 = make_float4(r[4] + bo[4], r[5] + bo[5], r[6] + bo[6], r[7] + bo[7]);
            *(float4*)(op)     = v0;
            *(float4*)(op + 4) = v1;
        }
    }
}

// ---------------------------------------------------------------------------
// Launch
// ---------------------------------------------------------------------------
extern "C" void kernel_launch(void* const* d_in, const int* in_sizes, int n_in,
                              void* d_out, int out_size) {
    const float4* inputs = (const float4*)d_in[0];
    const int*    rows   = (const int*)d_in[1];
    const int*    cols   = (const int*)d_in[2];
    const float*  vals   = (const float*)d_in[3];
    const float*  weight = (const float*)d_in[4];
    const float*  bias   = (const float*)d_in[5];
    float*        out    = (float*)d_out;

    cudaFuncSetAttribute(gemm_kernel, cudaFuncAttributeMaxDynamicSharedMemorySize,
                         GEMM_SMEM);

    pack_kernel<<<NN, 256>>>(inputs);
    rowptr_kernel<<<(EE + 255) / 256, 256>>>(rows);
    spmm_kernel<1><<<dim3(NN, 2), 128>>>(cols, vals);
    spmm_kernel<2><<<dim3(NN, 2), 128>>>(cols, vals);
    gemm_kernel<<<dim3((NN + 63) / 64, BB), 128, GEMM_SMEM>>>(weight, bias, out);
}

// round 5
// speedup vs baseline: 1.7265x; 1.1957x over previous
#include <cuda_runtime.h>
#include <cstdint>

// Problem constants
#define NN   20000
#define BB   16
#define FF   64
#define CC   1024
#define C4   256
#define EE   640000
#define ODIM 64
#define KDIM 192

// GEMM tile
#define BLK_M   64
#define AS_STR  196     // 192 + 4 pad (floats)
#define BS_STR  68      // 64 + 4 pad (floats)
#define GEMM_SMEM ((BLK_M * AS_STR + KDIM * BS_STR) * 4)   // 102,400 B

// Scratch (allocation-free rule: __device__ globals)
__device__ float g_x0[NN * CC];
__device__ float g_x1[NN * CC];
__device__ float g_x2[NN * CC];
__device__ int   g_rp[NN + 1];

__device__ __forceinline__ uint32_t to_tf32(float f) {
    uint32_t r; asm("cvt.rna.tf32.f32 %0, %1;" : "=r"(r) : "f"(f)); return r;
}

__device__ __forceinline__ void mma_tf32(float* d, const uint32_t* a, const uint32_t* b) {
    asm volatile(
        "mma.sync.aligned.m16n8k8.row.col.f32.tf32.tf32.f32 "
        "{%0,%1,%2,%3}, {%4,%5,%6,%7}, {%8,%9}, {%0,%1,%2,%3};"
        : "+f"(d[0]), "+f"(d[1]), "+f"(d[2]), "+f"(d[3])
        : "r"(a[0]), "r"(a[1]), "r"(a[2]), "r"(a[3]), "r"(b[0]), "r"(b[1]));
}

// ---------------------------------------------------------------------------
// 1) Pack inputs [B,N,F] -> x0 [N, B*F]
// ---------------------------------------------------------------------------
__global__ void pack_kernel(const float4* __restrict__ in4) {
    int g  = blockIdx.x * 256 + threadIdx.x;
    int f4 = g & 15;
    int b  = (g >> 4) & 15;
    int n  = g >> 8;
    ((float4*)g_x0)[g] = in4[(b * NN + n) * 16 + f4];
}

// ---------------------------------------------------------------------------
// 2) Row pointers from sorted rows
// ---------------------------------------------------------------------------
__global__ void rowptr_kernel(const int* __restrict__ rows) {
    int i = blockIdx.x * 256 + threadIdx.x;
    if (i >= EE) return;
    int r    = rows[i];
    int prev = (i == 0) ? -1 : rows[i - 1];
    for (int rr = prev + 1; rr <= r; rr++) g_rp[rr] = i;
    if (i == EE - 1) {
        for (int rr = r + 1; rr <= NN; rr++) g_rp[rr] = EE;
    }
}

// ---------------------------------------------------------------------------
// 3) SpMM (unchanged from R2): grid (NN,2), 128 threads, 1 float4/thread
// ---------------------------------------------------------------------------
template <int PHASE>
__global__ void __launch_bounds__(128) spmm_kernel(const int* __restrict__ cols,
                                                   const float* __restrict__ vals) {
    const float4* __restrict__ x = (const float4*)(PHASE == 1 ? g_x0 : g_x1);
    float4* __restrict__ y       = (float4*)(PHASE == 1 ? g_x1 : g_x2);

    int n = blockIdx.x;
    int t = threadIdx.x;
    int c = blockIdx.y * 128 + t;
    int s = g_rp[n];
    int e = g_rp[n + 1];

    __shared__ int   sc[128];
    __shared__ float sv[128];

    float4 acc = make_float4(0.f, 0.f, 0.f, 0.f);

    for (int base = s; base < e; base += 128) {
        int cnt = min(128, e - base);
        __syncthreads();
        if (t < cnt) {
            sc[t] = cols[base + t];
            sv[t] = vals[base + t];
        }
        __syncthreads();

        int j = 0;
        for (; j + 4 <= cnt; j += 4) {
            int4   c4 = *(const int4*)&sc[j];
            float4 v4 = *(const float4*)&sv[j];
            float4 x0v = x[c4.x * C4 + c];
            float4 x1v = x[c4.y * C4 + c];
            float4 x2v = x[c4.z * C4 + c];
            float4 x3v = x[c4.w * C4 + c];
            acc.x += v4.x * x0v.x; acc.y += v4.x * x0v.y;
            acc.z += v4.x * x0v.z; acc.w += v4.x * x0v.w;
            acc.x += v4.y * x1v.x; acc.y += v4.y * x1v.y;
            acc.z += v4.y * x1v.z; acc.w += v4.y * x1v.w;
            acc.x += v4.z * x2v.x; acc.y += v4.z * x2v.y;
            acc.z += v4.z * x2v.z; acc.w += v4.z * x2v.w;
            acc.x += v4.w * x3v.x; acc.y += v4.w * x3v.y;
            acc.z += v4.w * x3v.z; acc.w += v4.w * x3v.w;
        }
        for (; j < cnt; j++) {
            float  v  = sv[j];
            float4 xv = x[sc[j] * C4 + c];
            acc.x += v * xv.x; acc.y += v * xv.y;
            acc.z += v * xv.z; acc.w += v * xv.w;
        }
    }

    if (PHASE == 2) {
        float4 x0v = ((const float4*)g_x0)[n * C4 + c];
        acc.x = 2.f * acc.x - x0v.x;
        acc.y = 2.f * acc.y - x0v.y;
        acc.z = 2.f * acc.z - x0v.z;
        acc.w = 2.f * acc.w - x0v.w;
    }
    y[n * C4 + c] = acc;
}

// ---------------------------------------------------------------------------
// 4) GEMM via mma.sync tf32 (baseline PTX; tcgen05 rejected by compute_103)
//    out[(b*NN+n), o] = bias[o] + sum_k A[n,k]*Wp[k,o],  k = m*64+f
//    Block: 64 rows x 64 cols, 128 threads = 4 warps, warp = 32x32,
//    fragments m16n8k8, 24 K-steps. A/B pre-rounded to tf32 (cvt.rna).
// ---------------------------------------------------------------------------
__global__ void __launch_bounds__(128) gemm_mma_kernel(const float* __restrict__ weight,
                                                       const float* __restrict__ bias,
                                                       float* __restrict__ out) {
    extern __shared__ float sh[];
    float* As = sh;                          // [64][196]  k-major, tf32 bits
    float* Bs = sh + BLK_M * AS_STR;         // [192][68]  row k, col o, tf32 bits

    int t   = threadIdx.x;
    int wid = t >> 5;
    int lid = t & 31;
    int n0  = blockIdx.x * BLK_M;
    int b   = blockIdx.y;

    // Stage B with the (f*3+m) -> (k=m*64+f) row permutation
    for (int idx = t; idx < KDIM * 16; idx += 128) {
        int krow = idx >> 4;
        int o4   = idx & 15;
        int f    = krow & 63;
        int m    = krow >> 6;
        float4 w = ((const float4*)weight)[(f * 3 + m) * 16 + o4];
        uint4 wt;
        wt.x = to_tf32(w.x); wt.y = to_tf32(w.y);
        wt.z = to_tf32(w.z); wt.w = to_tf32(w.w);
        *(uint4*)(Bs + krow * BS_STR + o4 * 4) = wt;
    }

    // Stage A: row nl, cols k = m*64 + f  (from g_x0/g_x1/g_x2)
    const float* __restrict__ xs0 = g_x0;
    const float* __restrict__ xs1 = g_x1;
    const float* __restrict__ xs2 = g_x2;
    for (int idx = t; idx < BLK_M * 48; idx += 128) {
        int nl  = idx / 48;
        int seg = idx % 48;
        int m   = seg >> 4;
        int f4  = seg & 15;
        int n   = n0 + nl;
        float4 v = make_float4(0.f, 0.f, 0.f, 0.f);
        if (n < NN) {
            const float4* src = (const float4*)(m == 0 ? xs0 : (m == 1 ? xs1 : xs2));
            v = src[n * C4 + b * 16 + f4];
        }
        uint4 vt;
        vt.x = to_tf32(v.x); vt.y = to_tf32(v.y);
        vt.z = to_tf32(v.z); vt.w = to_tf32(v.w);
        *(uint4*)(As + nl * AS_STR + m * 64 + f4 * 4) = vt;
    }
    __syncthreads();

    int warp_m = wid & 1;                    // 2 m-warps
    int warp_n = wid >> 1;                   // 2 n-warps
    int m0  = warp_m * 32;
    int o0  = warp_n * 32;
    int grp = lid >> 2;                      // 0..7
    int tig = lid & 3;                       // 0..3

    float d[2][4][4];
    #pragma unroll
    for (int i = 0; i < 2; i++)
        #pragma unroll
        for (int j = 0; j < 4; j++)
            #pragma unroll
            for (int q = 0; q < 4; q++) d[i][j][q] = 0.f;

    const uint32_t* ap = (const uint32_t*)As;
    const uint32_t* bp = (const uint32_t*)Bs;

    #pragma unroll 4
    for (int ks = 0; ks < 24; ks++) {
        int k0 = ks * 8;
        uint32_t a[2][4], bf[4][2];
        #pragma unroll
        for (int i = 0; i < 2; i++) {
            int r = m0 + i * 16 + grp;
            a[i][0] = ap[r * AS_STR + k0 + tig];
            a[i][1] = ap[(r + 8) * AS_STR + k0 + tig];
            a[i][2] = ap[r * AS_STR + k0 + tig + 4];
            a[i][3] = ap[(r + 8) * AS_STR + k0 + tig + 4];
        }
        #pragma unroll
        for (int j = 0; j < 4; j++) {
            int c = o0 + j * 8 + grp;
            bf[j][0] = bp[(k0 + tig) * BS_STR + c];
            bf[j][1] = bp[(k0 + tig + 4) * BS_STR + c];
        }
        #pragma unroll
        for (int i = 0; i < 2; i++)
            #pragma unroll
            for (int j = 0; j < 4; j++)
                mma_tf32(d[i][j], a[i], bf[j]);
    }

    // Epilogue: d0/d1 -> (row grp, cols 2tig,2tig+1); d2/d3 -> row grp+8
    #pragma unroll
    for (int i = 0; i < 2; i++) {
        #pragma unroll
        for (int j = 0; j < 4; j++) {
            int cc = o0 + j * 8 + 2 * tig;
            float2 bb = *(const float2*)(bias + cc);
            int rn = n0 + m0 + i * 16 + grp;
            if (rn < NN) {
                float2 v = make_float2(d[i][j][0] + bb.x, d[i][j][1] + bb.y);
                *(float2*)(out + ((long long)b * NN + rn) * ODIM + cc) = v;
            }
            int rn2 = rn + 8;
            if (rn2 < NN) {
                float2 v = make_float2(d[i][j][2] + bb.x, d[i][j][3] + bb.y);
                *(float2*)(out + ((long long)b * NN + rn2) * ODIM + cc) = v;
            }
        }
    }
}

// ---------------------------------------------------------------------------
// Launch
// ---------------------------------------------------------------------------
extern "C" void kernel_launch(void* const* d_in, const int* in_sizes, int n_in,
                              void* d_out, int out_size) {
    const float4* inputs = (const float4*)d_in[0];
    const int*    rows   = (const int*)d_in[1];
    const int*    cols   = (const int*)d_in[2];
    const float*  vals   = (const float*)d_in[3];
    const float*  weight = (const float*)d_in[4];
    const float*  bias   = (const float*)d_in[5];
    float*        out    = (float*)d_out;

    cudaFuncSetAttribute(gemm_mma_kernel, cudaFuncAttributeMaxDynamicSharedMemorySize,
                         GEMM_SMEM);

    pack_kernel<<<NN, 256>>>(inputs);
    rowptr_kernel<<<(EE + 255) / 256, 256>>>(rows);
    spmm_kernel<1><<<dim3(NN, 2), 128>>>(cols, vals);
    spmm_kernel<2><<<dim3(NN, 2), 128>>>(cols, vals);
    gemm_mma_kernel<<<dim3((NN + BLK_M - 1) / BLK_M, BB), 128, GEMM_SMEM>>>(weight, bias, out);
}

// round 7
// speedup vs baseline: 3.6027x; 2.0867x over previous
#include <cuda_runtime.h>
#include <cuda_fp16.h>
#include <cstdint>

// Problem constants
#define NN   20000
#define BB   16
#define FF   64
#define CC   1024          // B*F columns of x
#define EE   640000
#define ODIM 64
#define KDIM 192

// GEMM tile: 128 rows x 64 cols, 256 threads (8 warps = 4m x 2n)
#define BLK_M    128
#define AS_STRH  200        // halves per A row (192 + 8 pad) -> 400 B
#define BS_STRH  72         // halves per B row (64 + 8 pad)  -> 144 B
#define GEMM_SMEM (BLK_M * AS_STRH * 2 + KDIM * BS_STRH * 2)   // 78,848 B

// Scratch (allocation-free rule: __device__ globals) — fp16 x arrays
__device__ __half g_x0[NN * CC];
__device__ __half g_x1[NN * CC];
__device__ __half g_x2[NN * CC];
__device__ int    g_rp[NN + 1];

__device__ __forceinline__ uint32_t smem_u32(const void* p) {
    uint32_t a;
    asm("{ .reg .u64 t; cvta.to.shared.u64 t, %1; cvt.u32.u64 %0, t; }" : "=r"(a) : "l"(p));
    return a;
}

__device__ __forceinline__ void mma_f16(float* d, const uint32_t* a, const uint32_t* b) {
    asm volatile(
        "mma.sync.aligned.m16n8k16.row.col.f32.f16.f16.f32 "
        "{%0,%1,%2,%3}, {%4,%5,%6,%7}, {%8,%9}, {%0,%1,%2,%3};"
        : "+f"(d[0]), "+f"(d[1]), "+f"(d[2]), "+f"(d[3])
        : "r"(a[0]), "r"(a[1]), "r"(a[2]), "r"(a[3]), "r"(b[0]), "r"(b[1]));
}
__device__ __forceinline__ void ldm_x4(uint32_t* r, uint32_t addr) {
    asm volatile("ldmatrix.sync.aligned.m8n8.x4.shared.b16 {%0,%1,%2,%3}, [%4];"
                 : "=r"(r[0]), "=r"(r[1]), "=r"(r[2]), "=r"(r[3]) : "r"(addr));
}
__device__ __forceinline__ void ldm_x4_t(uint32_t* r, uint32_t addr) {
    asm volatile("ldmatrix.sync.aligned.m8n8.x4.trans.shared.b16 {%0,%1,%2,%3}, [%4];"
                 : "=r"(r[0]), "=r"(r[1]), "=r"(r[2]), "=r"(r[3]) : "r"(addr));
}

// ---------------------------------------------------------------------------
// 1) Pack inputs [B,N,F] fp32 -> x0 [N, B*F] fp16.  One uint4 (8 halves) per
//    thread; halves [u*8, u*8+8) of row n, u = b*8 + f8.
// ---------------------------------------------------------------------------
__global__ void pack_kernel(const float4* __restrict__ in4) {
    int g  = blockIdx.x * 256 + threadIdx.x;   // 0 .. NN*128-1
    int f8 = g & 7;
    int b  = (g >> 3) & 15;
    int n  = g >> 7;
    float4 v0 = in4[(b * NN + n) * 16 + f8 * 2];
    float4 v1 = in4[(b * NN + n) * 16 + f8 * 2 + 1];
    __half2 h[4];
    h[0] = __float22half2_rn(make_float2(v0.x, v0.y));
    h[1] = __float22half2_rn(make_float2(v0.z, v0.w));
    h[2] = __float22half2_rn(make_float2(v1.x, v1.y));
    h[3] = __float22half2_rn(make_float2(v1.z, v1.w));
    ((uint4*)g_x0)[g] = *(uint4*)h;
}

// ---------------------------------------------------------------------------
// 2) Row pointers from sorted rows
// ---------------------------------------------------------------------------
__global__ void rowptr_kernel(const int* __restrict__ rows) {
    int i = blockIdx.x * 256 + threadIdx.x;
    if (i >= EE) return;
    int r    = rows[i];
    int prev = (i == 0) ? -1 : rows[i - 1];
    for (int rr = prev + 1; rr <= r; rr++) g_rp[rr] = i;
    if (i == EE - 1) {
        for (int rr = r + 1; rr <= NN; rr++) g_rp[rr] = EE;
    }
}

// ---------------------------------------------------------------------------
// 3) SpMM fp16: one block (128 threads) per row; thread owns 8 half cols
//    (one uint4). fp32 accumulation. PHASE1: x1 = A@x0; PHASE2: x2 = 2A@x1-x0
// ---------------------------------------------------------------------------
__device__ __forceinline__ void acc8(float* acc, uint4 xv, float v) {
    const __half2* h = (const __half2*)&xv;
    #pragma unroll
    for (int q = 0; q < 4; q++) {
        float2 f = __half22float2(h[q]);
        acc[q * 2]     += v * f.x;
        acc[q * 2 + 1] += v * f.y;
    }
}

template <int PHASE>
__global__ void __launch_bounds__(128) spmm_kernel(const int* __restrict__ cols,
                                                   const float* __restrict__ vals) {
    const uint4* __restrict__ x = (const uint4*)(PHASE == 1 ? g_x0 : g_x1);
    uint4* __restrict__ y       = (uint4*)(PHASE == 1 ? g_x1 : g_x2);

    int n = blockIdx.x;
    int t = threadIdx.x;                 // uint4 column 0..127
    int s = g_rp[n];
    int e = g_rp[n + 1];

    __shared__ int   sc[128];
    __shared__ float sv[128];

    float acc[8];
    #pragma unroll
    for (int q = 0; q < 8; q++) acc[q] = 0.f;

    for (int base = s; base < e; base += 128) {
        int cnt = min(128, e - base);
        __syncthreads();
        if (t < cnt) {
            sc[t] = cols[base + t];
            sv[t] = vals[base + t];
        }
        __syncthreads();

        int j = 0;
        for (; j + 4 <= cnt; j += 4) {
            int4   c4 = *(const int4*)&sc[j];
            float4 v4 = *(const float4*)&sv[j];
            uint4 x0v = x[c4.x * 128 + t];
            uint4 x1v = x[c4.y * 128 + t];
            uint4 x2v = x[c4.z * 128 + t];
            uint4 x3v = x[c4.w * 128 + t];
            acc8(acc, x0v, v4.x);
            acc8(acc, x1v, v4.y);
            acc8(acc, x2v, v4.z);
            acc8(acc, x3v, v4.w);
        }
        for (; j < cnt; j++) {
            uint4 xv = x[sc[j] * 128 + t];
            acc8(acc, xv, sv[j]);
        }
    }

    if (PHASE == 2) {
        uint4 x0v = ((const uint4*)g_x0)[n * 128 + t];
        const __half2* h = (const __half2*)&x0v;
        #pragma unroll
        for (int q = 0; q < 4; q++) {
            float2 f = __half22float2(h[q]);
            acc[q * 2]     = 2.f * acc[q * 2]     - f.x;
            acc[q * 2 + 1] = 2.f * acc[q * 2 + 1] - f.y;
        }
    }

    __half2 hr[4];
    #pragma unroll
    for (int q = 0; q < 4; q++)
        hr[q] = __float22half2_rn(make_float2(acc[q * 2], acc[q * 2 + 1]));
    y[n * 128 + t] = *(uint4*)hr;
}

// ---------------------------------------------------------------------------
// 4) GEMM fp16 mma m16n8k16 + ldmatrix.
//    out[(b*NN+n), o] = bias[o] + sum_k A[n,k]*Wp[k,o],  k = m*64+f
//    A (fp16) from g_xm rows, W rounded to fp16 with row permutation.
// ---------------------------------------------------------------------------
__global__ void __launch_bounds__(256) gemm_mma_kernel(const float* __restrict__ weight,
                                                       const float* __restrict__ bias,
                                                       float* __restrict__ out) {
    extern __shared__ char sh[];
    __half* As = (__half*)sh;                         // [128][200] halves
    __half* Bs = (__half*)(sh + BLK_M * AS_STRH * 2); // [192][72]  halves

    int t   = threadIdx.x;
    int wid = t >> 5;
    int lid = t & 31;
    int n0  = blockIdx.x * BLK_M;
    int b   = blockIdx.y;

    // Stage B: weight[(f*3+m)][o] fp32 -> Bs[k=m*64+f][o] fp16
    for (int idx = t; idx < KDIM * 16; idx += 256) {
        int krow = idx >> 4;
        int o4   = idx & 15;
        int f    = krow & 63;
        int m    = krow >> 6;
        float4 w = ((const float4*)weight)[(f * 3 + m) * 16 + o4];
        __half2 h2[2];
        h2[0] = __float22half2_rn(make_float2(w.x, w.y));
        h2[1] = __float22half2_rn(make_float2(w.z, w.w));
        *(uint2*)(Bs + krow * BS_STRH + o4 * 4) = *(uint2*)h2;
    }

    // Stage A: row nl, segment m (64 halves = 8 uint4) from g_xm[n*1024+b*64..]
    {
        const __half* __restrict__ xs0 = g_x0;
        const __half* __restrict__ xs1 = g_x1;
        const __half* __restrict__ xs2 = g_x2;
        for (int idx = t; idx < BLK_M * 24; idx += 256) {
            int q  = idx & 7;
            int m  = (idx >> 3) % 3;
            int nl = idx / 24;
            int n  = n0 + nl;
            uint4 v = make_uint4(0u, 0u, 0u, 0u);
            if (n < NN) {
                const __half* src = (m == 0 ? xs0 : (m == 1 ? xs1 : xs2));
                v = *(const uint4*)(src + n * CC + b * 64 + q * 8);
            }
            *(uint4*)(As + nl * AS_STRH + m * 64 + q * 8) = v;
        }
    }
    __syncthreads();

    int wm = wid & 3;                    // 4 m-warps
    int wn = wid >> 2;                   // 2 n-warps
    int grp = lid >> 2;                  // 0..7
    int tig = lid & 3;                   // 0..3

    // ldmatrix lane address components
    int tl = lid >> 3;                   // tile index 0..3
    int lr = (lid & 7) + (tl & 1) * 8;   // row within 16
    int lk = (tl >> 1) * 8;              // half-col offset within 16

    uint32_t As_base = smem_u32(As);
    uint32_t Bs_base = smem_u32(Bs);

    float d[2][4][4];
    #pragma unroll
    for (int i = 0; i < 2; i++)
        #pragma unroll
        for (int j = 0; j < 4; j++)
            #pragma unroll
            for (int q = 0; q < 4; q++) d[i][j][q] = 0.f;

    #pragma unroll 4
    for (int ks = 0; ks < 12; ks++) {
        int k0 = ks * 16;
        uint32_t a[2][4], bq[2][4];
        #pragma unroll
        for (int i = 0; i < 2; i++) {
            uint32_t addr = As_base + (uint32_t)((wm * 32 + i * 16 + lr) * (AS_STRH * 2)
                                                 + (k0 + lk) * 2);
            ldm_x4(a[i], addr);
        }
        #pragma unroll
        for (int jj = 0; jj < 2; jj++) {
            uint32_t addr = Bs_base + (uint32_t)((k0 + lr) * (BS_STRH * 2)
                                                 + (wn * 32 + jj * 16 + lk) * 2);
            ldm_x4_t(bq[jj], addr);
        }
        #pragma unroll
        for (int i = 0; i < 2; i++) {
            #pragma unroll
            for (int j = 0; j < 4; j++) {
                uint32_t bb[2] = { bq[j >> 1][(j & 1) * 2], bq[j >> 1][(j & 1) * 2 + 1] };
                mma_f16(d[i][j], a[i], bb);
            }
        }
    }

    // Epilogue
    #pragma unroll
    for (int i = 0; i < 2; i++) {
        #pragma unroll
        for (int j = 0; j < 4; j++) {
            int cc = wn * 32 + j * 8 + 2 * tig;
            float2 bb = *(const float2*)(bias + cc);
            int rn = n0 + wm * 32 + i * 16 + grp;
            if (rn < NN) {
                float2 v = make_float2(d[i][j][0] + bb.x, d[i][j][1] + bb.y);
                *(float2*)(out + ((long long)b * NN + rn) * ODIM + cc) = v;
            }
            int rn2 = rn + 8;
            if (rn2 < NN) {
                float2 v = make_float2(d[i][j][2] + bb.x, d[i][j][3] + bb.y);
                *(float2*)(out + ((long long)b * NN + rn2) * ODIM + cc) = v;
            }
        }
    }
}

// ---------------------------------------------------------------------------
// Launch
// ---------------------------------------------------------------------------
extern "C" void kernel_launch(void* const* d_in, const int* in_sizes, int n_in,
                              void* d_out, int out_size) {
    const float4* inputs = (const float4*)d_in[0];
    const int*    rows   = (const int*)d_in[1];
    const int*    cols   = (const int*)d_in[2];
    const float*  vals   = (const float*)d_in[3];
    const float*  weight = (const float*)d_in[4];
    const float*  bias   = (const float*)d_in[5];
    float*        out    = (float*)d_out;

    cudaFuncSetAttribute(gemm_mma_kernel, cudaFuncAttributeMaxDynamicSharedMemorySize,
                         GEMM_SMEM);

    pack_kernel<<<NN * 128 / 256, 256>>>(inputs);
    rowptr_kernel<<<(EE + 255) / 256, 256>>>(rows);
    spmm_kernel<1><<<NN, 128>>>(cols, vals);
    spmm_kernel<2><<<NN, 128>>>(cols, vals);
    gemm_mma_kernel<<<dim3((NN + BLK_M - 1) / BLK_M, BB), 256, GEMM_SMEM>>>(weight, bias, out);
}

// round 9
// speedup vs baseline: 4.6749x; 1.2976x over previous
#include <cuda_runtime.h>
#include <cuda_fp16.h>
#include <cstdint>

// Problem constants
#define NN   20000
#define BB   16
#define FF   64
#define CC   1024          // B*F columns of x
#define EE   640000
#define ODIM 64
#define KDIM 192

// GEMM tile: 128 rows x 64 cols, 256 threads (8 warps = 4m x 2n)
#define BLK_M    128
#define AS_STRH  200        // halves per A row (192 + 8 pad) -> 400 B
#define BS_STRH  72         // halves per B row (64 + 8 pad)  -> 144 B
#define GEMM_SMEM (BLK_M * AS_STRH * 2 + KDIM * BS_STRH * 2)   // 78,848 B

// Scratch (allocation-free rule: __device__ globals) — fp16 x arrays
__device__ __half g_x0[NN * CC];
__device__ __half g_x1[NN * CC];
__device__ __half g_x2[NN * CC];
__device__ int    g_rp[NN + 1];

__device__ __forceinline__ uint32_t smem_u32(const void* p) {
    uint32_t a;
    asm("{ .reg .u64 t; cvta.to.shared.u64 t, %1; cvt.u32.u64 %0, t; }" : "=r"(a) : "l"(p));
    return a;
}

__device__ __forceinline__ void mma_f16(float* d, const uint32_t* a, const uint32_t* b) {
    asm volatile(
        "mma.sync.aligned.m16n8k16.row.col.f32.f16.f16.f32 "
        "{%0,%1,%2,%3}, {%4,%5,%6,%7}, {%8,%9}, {%0,%1,%2,%3};"
        : "+f"(d[0]), "+f"(d[1]), "+f"(d[2]), "+f"(d[3])
        : "r"(a[0]), "r"(a[1]), "r"(a[2]), "r"(a[3]), "r"(b[0]), "r"(b[1]));
}
__device__ __forceinline__ void ldm_x4(uint32_t* r, uint32_t addr) {
    asm volatile("ldmatrix.sync.aligned.m8n8.x4.shared.b16 {%0,%1,%2,%3}, [%4];"
                 : "=r"(r[0]), "=r"(r[1]), "=r"(r[2]), "=r"(r[3]) : "r"(addr));
}
__device__ __forceinline__ void ldm_x4_t(uint32_t* r, uint32_t addr) {
    asm volatile("ldmatrix.sync.aligned.m8n8.x4.trans.shared.b16 {%0,%1,%2,%3}, [%4];"
                 : "=r"(r[0]), "=r"(r[1]), "=r"(r[2]), "=r"(r[3]) : "r"(addr));
}
__device__ __forceinline__ void cp_async16(uint32_t dst, const void* src, int src_bytes) {
    asm volatile("cp.async.ca.shared.global [%0], [%1], 16, %2;"
                 :: "r"(dst), "l"(src), "r"(src_bytes));
}
#define CP_COMMIT() asm volatile("cp.async.commit_group;" ::: "memory")
#define CP_WAIT0()  asm volatile("cp.async.wait_group 0;" ::: "memory")

// ---------------------------------------------------------------------------
// 1) Pack inputs [B,N,F] fp32 -> x0 [N, B*F] fp16
// ---------------------------------------------------------------------------
__global__ void pack_kernel(const float4* __restrict__ in4) {
    int g  = blockIdx.x * 256 + threadIdx.x;   // 0 .. NN*128-1
    int f8 = g & 7;
    int b  = (g >> 3) & 15;
    int n  = g >> 7;
    float4 v0 = in4[(b * NN + n) * 16 + f8 * 2];
    float4 v1 = in4[(b * NN + n) * 16 + f8 * 2 + 1];
    __half2 h[4];
    h[0] = __float22half2_rn(make_float2(v0.x, v0.y));
    h[1] = __float22half2_rn(make_float2(v0.z, v0.w));
    h[2] = __float22half2_rn(make_float2(v1.x, v1.y));
    h[3] = __float22half2_rn(make_float2(v1.z, v1.w));
    ((uint4*)g_x0)[g] = *(uint4*)h;
}

// ---------------------------------------------------------------------------
// 2) Row pointers from sorted rows
// ---------------------------------------------------------------------------
__global__ void rowptr_kernel(const int* __restrict__ rows) {
    int i = blockIdx.x * 256 + threadIdx.x;
    if (i >= EE) return;
    int r    = rows[i];
    int prev = (i == 0) ? -1 : rows[i - 1];
    for (int rr = prev + 1; rr <= r; rr++) g_rp[rr] = i;
    if (i == EE - 1) {
        for (int rr = r + 1; rr <= NN; rr++) g_rp[rr] = EE;
    }
}

// ---------------------------------------------------------------------------
// 3) SpMM fp16: one block (128 threads) per row; thread owns 8 half cols.
//    4-edge chunks accumulated in __half2 (HMUL2 + 3x HFMA2), flushed to
//    fp32 accumulators each chunk. vals staged as half2(v,v) in smem.
// ---------------------------------------------------------------------------
template <int PHASE>
__global__ void __launch_bounds__(128) spmm_kernel(const int* __restrict__ cols,
                                                   const float* __restrict__ vals) {
    const uint4* __restrict__ x = (const uint4*)(PHASE == 1 ? g_x0 : g_x1);
    uint4* __restrict__ y       = (uint4*)(PHASE == 1 ? g_x1 : g_x2);

    int n = blockIdx.x;
    int t = threadIdx.x;                 // uint4 column 0..127
    int s = g_rp[n];
    int e = g_rp[n + 1];

    __shared__ int sc[128];
    __shared__ __align__(16) __half2 svh[128];

    float acc[8];
    #pragma unroll
    for (int q = 0; q < 8; q++) acc[q] = 0.f;

    for (int base = s; base < e; base += 128) {
        int cnt = min(128, e - base);
        __syncthreads();
        if (t < cnt) {
            sc[t]  = cols[base + t];
            svh[t] = __float2half2_rn(vals[base + t]);
        }
        __syncthreads();

        int j = 0;
        for (; j + 4 <= cnt; j += 4) {
            int4  c4 = *(const int4*)&sc[j];
            uint4 vv = *(const uint4*)&svh[j];
            __half2 va = *(const __half2*)&vv.x;
            __half2 vb = *(const __half2*)&vv.y;
            __half2 vc = *(const __half2*)&vv.z;
            __half2 vd = *(const __half2*)&vv.w;
            uint4 x0v = x[c4.x * 128 + t];
            uint4 x1v = x[c4.y * 128 + t];
            uint4 x2v = x[c4.z * 128 + t];
            uint4 x3v = x[c4.w * 128 + t];
            const __half2* h0 = (const __half2*)&x0v;
            const __half2* h1 = (const __half2*)&x1v;
            const __half2* h2 = (const __half2*)&x2v;
            const __half2* h3 = (const __half2*)&x3v;
            #pragma unroll
            for (int q = 0; q < 4; q++) {
                __half2 h = __hmul2(h0[q], va);
                h = __hfma2(h1[q], vb, h);
                h = __hfma2(h2[q], vc, h);
                h = __hfma2(h3[q], vd, h);
                float2 f = __half22float2(h);
                acc[q * 2]     += f.x;
                acc[q * 2 + 1] += f.y;
            }
        }
        for (; j < cnt; j++) {
            __half2 va = svh[j];
            uint4 xv = x[sc[j] * 128 + t];
            const __half2* h = (const __half2*)&xv;
            #pragma unroll
            for (int q = 0; q < 4; q++) {
                float2 f = __half22float2(__hmul2(h[q], va));
                acc[q * 2]     += f.x;
                acc[q * 2 + 1] += f.y;
            }
        }
    }

    if (PHASE == 2) {
        uint4 x0v = ((const uint4*)g_x0)[n * 128 + t];
        const __half2* h = (const __half2*)&x0v;
        #pragma unroll
        for (int q = 0; q < 4; q++) {
            float2 f = __half22float2(h[q]);
            acc[q * 2]     = 2.f * acc[q * 2]     - f.x;
            acc[q * 2 + 1] = 2.f * acc[q * 2 + 1] - f.y;
        }
    }

    __half2 hr[4];
    #pragma unroll
    for (int q = 0; q < 4; q++)
        hr[q] = __float22half2_rn(make_float2(acc[q * 2], acc[q * 2 + 1]));
    y[n * 128 + t] = *(uint4*)hr;
}

// ---------------------------------------------------------------------------
// 4) GEMM fp16 mma m16n8k16 + ldmatrix; A staged via cp.async.
// ---------------------------------------------------------------------------
__global__ void __launch_bounds__(256) gemm_mma_kernel(const float* __restrict__ weight,
                                                       const float* __restrict__ bias,
                                                       float* __restrict__ out) {
    extern __shared__ char sh[];
    __half* As = (__half*)sh;                         // [128][200] halves
    __half* Bs = (__half*)(sh + BLK_M * AS_STRH * 2); // [192][72]  halves

    int t   = threadIdx.x;
    int wid = t >> 5;
    int lid = t & 31;
    int n0  = blockIdx.x * BLK_M;
    int b   = blockIdx.y;

    uint32_t As_base = smem_u32(As);
    uint32_t Bs_base = smem_u32(Bs);

    // Stage A via cp.async: row nl, segment m (8 uint4 each)
    {
        const __half* __restrict__ xs0 = g_x0;
        const __half* __restrict__ xs1 = g_x1;
        const __half* __restrict__ xs2 = g_x2;
        for (int idx = t; idx < BLK_M * 24; idx += 256) {
            int q  = idx & 7;
            int m  = (idx >> 3) % 3;
            int nl = idx / 24;
            int n  = n0 + nl;
            const __half* src = (m == 0 ? xs0 : (m == 1 ? xs1 : xs2));
            int nc = n < NN ? n : 0;
            uint32_t dst = As_base + (uint32_t)(nl * AS_STRH + m * 64 + q * 8) * 2;
            cp_async16(dst, src + (size_t)nc * CC + b * 64 + q * 8, n < NN ? 16 : 0);
        }
        CP_COMMIT();
    }

    // Stage B: weight[(f*3+m)][o] fp32 -> Bs[k=m*64+f][o] fp16
    for (int idx = t; idx < KDIM * 16; idx += 256) {
        int krow = idx >> 4;
        int o4   = idx & 15;
        int f    = krow & 63;
        int m    = krow >> 6;
        float4 w = ((const float4*)weight)[(f * 3 + m) * 16 + o4];
        __half2 h2[2];
        h2[0] = __float22half2_rn(make_float2(w.x, w.y));
        h2[1] = __float22half2_rn(make_float2(w.z, w.w));
        *(uint2*)(Bs + krow * BS_STRH + o4 * 4) = *(uint2*)h2;
    }
    CP_WAIT0();
    __syncthreads();

    int wm = wid & 3;                    // 4 m-warps
    int wn = wid >> 2;                   // 2 n-warps
    int grp = lid >> 2;                  // 0..7
    int tig = lid & 3;                   // 0..3

    // ldmatrix lane address components
    int tl = lid >> 3;                   // tile index 0..3
    int lr = (lid & 7) + (tl & 1) * 8;   // row within 16
    int lk = (tl >> 1) * 8;              // half-col offset within 16

    float d[2][4][4];
    #pragma unroll
    for (int i = 0; i < 2; i++)
        #pragma unroll
        for (int j = 0; j < 4; j++)
            #pragma unroll
            for (int q = 0; q < 4; q++) d[i][j][q] = 0.f;

    #pragma unroll 4
    for (int ks = 0; ks < 12; ks++) {
        int k0 = ks * 16;
        uint32_t a[2][4], bq[2][4];
        #pragma unroll
        for (int i = 0; i < 2; i++) {
            uint32_t addr = As_base + (uint32_t)((wm * 32 + i * 16 + lr) * (AS_STRH * 2)
                                                 + (k0 + lk) * 2);
            ldm_x4(a[i], addr);
        }
        #pragma unroll
        for (int jj = 0; jj < 2; jj++) {
            uint32_t addr = Bs_base + (uint32_t)((k0 + lr) * (BS_STRH * 2)
                                                 + (wn * 32 + jj * 16 + lk) * 2);
            ldm_x4_t(bq[jj], addr);
        }
        #pragma unroll
        for (int i = 0; i < 2; i++) {
            #pragma unroll
            for (int j = 0; j < 4; j++) {
                uint32_t bb[2] = { bq[j >> 1][(j & 1) * 2], bq[j >> 1][(j & 1) * 2 + 1] };
                mma_f16(d[i][j], a[i], bb);
            }
        }
    }

    // Epilogue
    #pragma unroll
    for (int i = 0; i < 2; i++) {
        #pragma unroll
        for (int j = 0; j < 4; j++) {
            int cc = wn * 32 + j * 8 + 2 * tig;
            float2 bb = *(const float2*)(bias + cc);
            int rn = n0 + wm * 32 + i * 16 + grp;
            if (rn < NN) {
                float2 v = make_float2(d[i][j][0] + bb.x, d[i][j][1] + bb.y);
                *(float2*)(out + ((long long)b * NN + rn) * ODIM + cc) = v;
            }
            int rn2 = rn + 8;
            if (rn2 < NN) {
                float2 v = make_float2(d[i][j][2] + bb.x, d[i][j][3] + bb.y);
                *(float2*)(out + ((long long)b * NN + rn2) * ODIM + cc) = v;
            }
        }
    }
}

// ---------------------------------------------------------------------------
// Launch
// ---------------------------------------------------------------------------
extern "C" void kernel_launch(void* const* d_in, const int* in_sizes, int n_in,
                              void* d_out, int out_size) {
    const float4* inputs = (const float4*)d_in[0];
    const int*    rows   = (const int*)d_in[1];
    const int*    cols   = (const int*)d_in[2];
    const float*  vals   = (const float*)d_in[3];
    const float*  weight = (const float*)d_in[4];
    const float*  bias   = (const float*)d_in[5];
    float*        out    = (float*)d_out;

    cudaFuncSetAttribute(gemm_mma_kernel, cudaFuncAttributeMaxDynamicSharedMemorySize,
                         GEMM_SMEM);

    pack_kernel<<<NN * 128 / 256, 256>>>(inputs);
    rowptr_kernel<<<(EE + 255) / 256, 256>>>(rows);
    spmm_kernel<1><<<NN, 128>>>(cols, vals);
    spmm_kernel<2><<<NN, 128>>>(cols, vals);
    gemm_mma_kernel<<<dim3((NN + BLK_M - 1) / BLK_M, BB), 256, GEMM_SMEM>>>(weight, bias, out);
}

// round 10
// speedup vs baseline: 4.8028x; 1.0274x over previous
#include <cuda_runtime.h>
#include <cuda_fp16.h>
#include <cstdint>

// Problem constants
#define NN   20000
#define BB   16
#define FF   64
#define CC   1024          // B*F columns of x
#define EE   640000
#define ODIM 64
#define KDIM 192

// GEMM tile: 128 rows x 64 cols, 256 threads (8 warps = 4m x 2n)
#define BLK_M    128
#define AS_STRH  200        // halves per A row (192 + 8 pad) -> 400 B
#define BS_STRH  72         // halves per B row (64 + 8 pad)  -> 144 B
#define A_BUF_H  (BLK_M * AS_STRH)                       // halves per A buffer
#define GEMM_SMEM (2 * A_BUF_H * 2 + KDIM * BS_STRH * 2) // 129,664 B

// Scratch (allocation-free rule: __device__ globals) — fp16 x arrays
__device__ __half g_x0[NN * CC];
__device__ __half g_x1[NN * CC];
__device__ __half g_x2[NN * CC];
__device__ int    g_rp[NN + 1];

__device__ __forceinline__ uint32_t smem_u32(const void* p) {
    uint32_t a;
    asm("{ .reg .u64 t; cvta.to.shared.u64 t, %1; cvt.u32.u64 %0, t; }" : "=r"(a) : "l"(p));
    return a;
}

__device__ __forceinline__ void mma_f16(float* d, const uint32_t* a, const uint32_t* b) {
    asm volatile(
        "mma.sync.aligned.m16n8k16.row.col.f32.f16.f16.f32 "
        "{%0,%1,%2,%3}, {%4,%5,%6,%7}, {%8,%9}, {%0,%1,%2,%3};"
        : "+f"(d[0]), "+f"(d[1]), "+f"(d[2]), "+f"(d[3])
        : "r"(a[0]), "r"(a[1]), "r"(a[2]), "r"(a[3]), "r"(b[0]), "r"(b[1]));
}
__device__ __forceinline__ void ldm_x4(uint32_t* r, uint32_t addr) {
    asm volatile("ldmatrix.sync.aligned.m8n8.x4.shared.b16 {%0,%1,%2,%3}, [%4];"
                 : "=r"(r[0]), "=r"(r[1]), "=r"(r[2]), "=r"(r[3]) : "r"(addr));
}
__device__ __forceinline__ void ldm_x4_t(uint32_t* r, uint32_t addr) {
    asm volatile("ldmatrix.sync.aligned.m8n8.x4.trans.shared.b16 {%0,%1,%2,%3}, [%4];"
                 : "=r"(r[0]), "=r"(r[1]), "=r"(r[2]), "=r"(r[3]) : "r"(addr));
}
__device__ __forceinline__ void cp_async16(uint32_t dst, const void* src, int src_bytes) {
    asm volatile("cp.async.ca.shared.global [%0], [%1], 16, %2;"
                 :: "r"(dst), "l"(src), "r"(src_bytes));
}
#define CP_COMMIT() asm volatile("cp.async.commit_group;" ::: "memory")
#define CP_WAIT0()  asm volatile("cp.async.wait_group 0;" ::: "memory")
#define CP_WAIT1()  asm volatile("cp.async.wait_group 1;" ::: "memory")

// ---------------------------------------------------------------------------
// 1) Pack inputs [B,N,F] fp32 -> x0 [N, B*F] fp16
// ---------------------------------------------------------------------------
__global__ void pack_kernel(const float4* __restrict__ in4) {
    int g  = blockIdx.x * 256 + threadIdx.x;   // 0 .. NN*128-1
    int f8 = g & 7;
    int b  = (g >> 3) & 15;
    int n  = g >> 7;
    float4 v0 = in4[(b * NN + n) * 16 + f8 * 2];
    float4 v1 = in4[(b * NN + n) * 16 + f8 * 2 + 1];
    __half2 h[4];
    h[0] = __float22half2_rn(make_float2(v0.x, v0.y));
    h[1] = __float22half2_rn(make_float2(v0.z, v0.w));
    h[2] = __float22half2_rn(make_float2(v1.x, v1.y));
    h[3] = __float22half2_rn(make_float2(v1.z, v1.w));
    ((uint4*)g_x0)[g] = *(uint4*)h;
}

// ---------------------------------------------------------------------------
// 2) Row pointers from sorted rows
// ---------------------------------------------------------------------------
__global__ void rowptr_kernel(const int* __restrict__ rows) {
    int i = blockIdx.x * 256 + threadIdx.x;
    if (i >= EE) return;
    int r    = rows[i];
    int prev = (i == 0) ? -1 : rows[i - 1];
    for (int rr = prev + 1; rr <= r; rr++) g_rp[rr] = i;
    if (i == EE - 1) {
        for (int rr = r + 1; rr <= NN; rr++) g_rp[rr] = EE;
    }
}

// ---------------------------------------------------------------------------
// 3) SpMM fp16: block (128 thr) per row; thread owns 8 half cols (1 uint4).
//    8-edge chunks: 8 gathers in flight (MLP=8), consumed as TWO independent
//    4-deep half2 chains flushed separately to fp32 (same rounding depth as
//    the proven chunk-4 version).
// ---------------------------------------------------------------------------
template <int PHASE>
__global__ void __launch_bounds__(128) spmm_kernel(const int* __restrict__ cols,
                                                   const float* __restrict__ vals) {
    const uint4* __restrict__ x = (const uint4*)(PHASE == 1 ? g_x0 : g_x1);
    uint4* __restrict__ y       = (uint4*)(PHASE == 1 ? g_x1 : g_x2);

    int n = blockIdx.x;
    int t = threadIdx.x;                 // uint4 column 0..127
    int s = g_rp[n];
    int e = g_rp[n + 1];

    __shared__ int sc[128];
    __shared__ __align__(16) __half2 svh[128];

    float acc[8];
    #pragma unroll
    for (int q = 0; q < 8; q++) acc[q] = 0.f;

    for (int base = s; base < e; base += 128) {
        int cnt = min(128, e - base);
        __syncthreads();
        if (t < cnt) {
            sc[t]  = cols[base + t];
            svh[t] = __float2half2_rn(vals[base + t]);
        }
        __syncthreads();

        int j = 0;
        for (; j + 8 <= cnt; j += 8) {
            int cidx[8];
            *(int4*)&cidx[0] = *(const int4*)&sc[j];
            *(int4*)&cidx[4] = *(const int4*)&sc[j + 4];
            __half2 v[8];
            *(uint4*)&v[0] = *(const uint4*)&svh[j];
            *(uint4*)&v[4] = *(const uint4*)&svh[j + 4];
            uint4 xv[8];
            #pragma unroll
            for (int ee = 0; ee < 8; ee++) xv[ee] = x[cidx[ee] * 128 + t];
            #pragma unroll
            for (int q = 0; q < 4; q++) {
                __half2 ha = __hmul2(((const __half2*)&xv[0])[q], v[0]);
                __half2 hb = __hmul2(((const __half2*)&xv[4])[q], v[4]);
                #pragma unroll
                for (int ee = 1; ee < 4; ee++) {
                    ha = __hfma2(((const __half2*)&xv[ee])[q], v[ee], ha);
                    hb = __hfma2(((const __half2*)&xv[ee + 4])[q], v[ee + 4], hb);
                }
                float2 fa = __half22float2(ha);
                float2 fb = __half22float2(hb);
                acc[q * 2]     += fa.x + fb.x;
                acc[q * 2 + 1] += fa.y + fb.y;
            }
        }
        for (; j + 4 <= cnt; j += 4) {
            int4 c4 = *(const int4*)&sc[j];
            __half2 v[4];
            *(uint4*)&v[0] = *(const uint4*)&svh[j];
            uint4 xv[4];
            xv[0] = x[c4.x * 128 + t];
            xv[1] = x[c4.y * 128 + t];
            xv[2] = x[c4.z * 128 + t];
            xv[3] = x[c4.w * 128 + t];
            #pragma unroll
            for (int q = 0; q < 4; q++) {
                __half2 h = __hmul2(((const __half2*)&xv[0])[q], v[0]);
                h = __hfma2(((const __half2*)&xv[1])[q], v[1], h);
                h = __hfma2(((const __half2*)&xv[2])[q], v[2], h);
                h = __hfma2(((const __half2*)&xv[3])[q], v[3], h);
                float2 f = __half22float2(h);
                acc[q * 2]     += f.x;
                acc[q * 2 + 1] += f.y;
            }
        }
        for (; j < cnt; j++) {
            __half2 va = svh[j];
            uint4 xv = x[sc[j] * 128 + t];
            const __half2* h = (const __half2*)&xv;
            #pragma unroll
            for (int q = 0; q < 4; q++) {
                float2 f = __half22float2(__hmul2(h[q], va));
                acc[q * 2]     += f.x;
                acc[q * 2 + 1] += f.y;
            }
        }
    }

    if (PHASE == 2) {
        uint4 x0v = ((const uint4*)g_x0)[n * 128 + t];
        const __half2* h = (const __half2*)&x0v;
        #pragma unroll
        for (int q = 0; q < 4; q++) {
            float2 f = __half22float2(h[q]);
            acc[q * 2]     = 2.f * acc[q * 2]     - f.x;
            acc[q * 2 + 1] = 2.f * acc[q * 2 + 1] - f.y;
        }
    }

    __half2 hr[4];
    #pragma unroll
    for (int q = 0; q < 4; q++)
        hr[q] = __float22half2_rn(make_float2(acc[q * 2], acc[q * 2 + 1]));
    y[n * 128 + t] = *(uint4*)hr;
}

// ---------------------------------------------------------------------------
// 4) GEMM fp16 mma m16n8k16 + ldmatrix.
//    Block loops over 4 batch values: B (weights) staged once; A double-
//    buffered via cp.async so A(bi+1) streams while bi computes.
// ---------------------------------------------------------------------------
__device__ __forceinline__ void prefetch_A(uint32_t As_dst, int n0, int b, int t) {
    const __half* __restrict__ xs0 = g_x0;
    const __half* __restrict__ xs1 = g_x1;
    const __half* __restrict__ xs2 = g_x2;
    for (int idx = t; idx < BLK_M * 24; idx += 256) {
        int q  = idx & 7;
        int m  = (idx >> 3) % 3;
        int nl = idx / 24;
        int n  = n0 + nl;
        const __half* src = (m == 0 ? xs0 : (m == 1 ? xs1 : xs2));
        int nc = n < NN ? n : 0;
        uint32_t dst = As_dst + (uint32_t)(nl * AS_STRH + m * 64 + q * 8) * 2;
        cp_async16(dst, src + (size_t)nc * CC + b * 64 + q * 8, n < NN ? 16 : 0);
    }
    CP_COMMIT();
}

__global__ void __launch_bounds__(256) gemm_mma_kernel(const float* __restrict__ weight,
                                                       const float* __restrict__ bias,
                                                       float* __restrict__ out) {
    extern __shared__ char sh[];
    __half* Bs = (__half*)(sh + 2 * A_BUF_H * 2);     // [192][72] halves

    int t   = threadIdx.x;
    int wid = t >> 5;
    int lid = t & 31;
    int n0  = blockIdx.x * BLK_M;
    int b0  = blockIdx.y * 4;

    uint32_t As_base = smem_u32(sh);                  // buffer 0; buffer 1 at +A_BUF_H*2
    uint32_t Bs_base = smem_u32(Bs);

    // Prefetch A(b0) into buffer 0
    prefetch_A(As_base, n0, b0, t);

    // Stage B once: weight[(f*3+m)][o] fp32 -> Bs[k=m*64+f][o] fp16
    for (int idx = t; idx < KDIM * 16; idx += 256) {
        int krow = idx >> 4;
        int o4   = idx & 15;
        int f    = krow & 63;
        int m    = krow >> 6;
        float4 w = ((const float4*)weight)[(f * 3 + m) * 16 + o4];
        __half2 h2[2];
        h2[0] = __float22half2_rn(make_float2(w.x, w.y));
        h2[1] = __float22half2_rn(make_float2(w.z, w.w));
        *(uint2*)(Bs + krow * BS_STRH + o4 * 4) = *(uint2*)h2;
    }

    int wm = wid & 3;                    // 4 m-warps
    int wn = wid >> 2;                   // 2 n-warps
    int grp = lid >> 2;                  // 0..7
    int tig = lid & 3;                   // 0..3
    int tl = lid >> 3;                   // ldmatrix tile 0..3
    int lr = (lid & 7) + (tl & 1) * 8;   // row within 16
    int lk = (tl >> 1) * 8;              // half-col offset within 16

    for (int bi = 0; bi < 4; bi++) {
        int b = b0 + bi;
        uint32_t As_cur = As_base + (uint32_t)(bi & 1) * (A_BUF_H * 2);

        if (bi < 3) {
            prefetch_A(As_base + (uint32_t)((bi + 1) & 1) * (A_BUF_H * 2), n0, b + 1, t);
            CP_WAIT1();
        } else {
            CP_WAIT0();
        }
        __syncthreads();

        float d[2][4][4];
        #pragma unroll
        for (int i = 0; i < 2; i++)
            #pragma unroll
            for (int j = 0; j < 4; j++)
                #pragma unroll
                for (int q = 0; q < 4; q++) d[i][j][q] = 0.f;

        #pragma unroll 4
        for (int ks = 0; ks < 12; ks++) {
            int k0 = ks * 16;
            uint32_t a[2][4], bq[2][4];
            #pragma unroll
            for (int i = 0; i < 2; i++) {
                uint32_t addr = As_cur + (uint32_t)((wm * 32 + i * 16 + lr) * (AS_STRH * 2)
                                                     + (k0 + lk) * 2);
                ldm_x4(a[i], addr);
            }
            #pragma unroll
            for (int jj = 0; jj < 2; jj++) {
                uint32_t addr = Bs_base + (uint32_t)((k0 + lr) * (BS_STRH * 2)
                                                     + (wn * 32 + jj * 16 + lk) * 2);
                ldm_x4_t(bq[jj], addr);
            }
            #pragma unroll
            for (int i = 0; i < 2; i++) {
                #pragma unroll
                for (int j = 0; j < 4; j++) {
                    uint32_t bb[2] = { bq[j >> 1][(j & 1) * 2], bq[j >> 1][(j & 1) * 2 + 1] };
                    mma_f16(d[i][j], a[i], bb);
                }
            }
        }

        // Epilogue
        #pragma unroll
        for (int i = 0; i < 2; i++) {
            #pragma unroll
            for (int j = 0; j < 4; j++) {
                int cc = wn * 32 + j * 8 + 2 * tig;
                float2 bb = *(const float2*)(bias + cc);
                int rn = n0 + wm * 32 + i * 16 + grp;
                if (rn < NN) {
                    float2 v = make_float2(d[i][j][0] + bb.x, d[i][j][1] + bb.y);
                    *(float2*)(out + ((long long)b * NN + rn) * ODIM + cc) = v;
                }
                int rn2 = rn + 8;
                if (rn2 < NN) {
                    float2 v = make_float2(d[i][j][2] + bb.x, d[i][j][3] + bb.y);
                    *(float2*)(out + ((long long)b * NN + rn2) * ODIM + cc) = v;
                }
            }
        }
        __syncthreads();   // protect A buffer reuse before next prefetch consumes it
    }
}

// ---------------------------------------------------------------------------
// Launch
// ---------------------------------------------------------------------------
extern "C" void kernel_launch(void* const* d_in, const int* in_sizes, int n_in,
                              void* d_out, int out_size) {
    const float4* inputs = (const float4*)d_in[0];
    const int*    rows   = (const int*)d_in[1];
    const int*    cols   = (const int*)d_in[2];
    const float*  vals   = (const float*)d_in[3];
    const float*  weight = (const float*)d_in[4];
    const float*  bias   = (const float*)d_in[5];
    float*        out    = (float*)d_out;

    cudaFuncSetAttribute(gemm_mma_kernel, cudaFuncAttributeMaxDynamicSharedMemorySize,
                         GEMM_SMEM);

    pack_kernel<<<NN * 128 / 256, 256>>>(inputs);
    rowptr_kernel<<<(EE + 255) / 256, 256>>>(rows);
    spmm_kernel<1><<<NN, 128>>>(cols, vals);
    spmm_kernel<2><<<NN, 128>>>(cols, vals);
    gemm_mma_kernel<<<dim3((NN + BLK_M - 1) / BLK_M, 4), 256, GEMM_SMEM>>>(weight, bias, out);
}

// round 13
// speedup vs baseline: 5.1178x; 1.0656x over previous
#include <cuda_runtime.h>
#include <cuda_fp16.h>
#include <cstdint>

// Problem constants
#define NN   20000
#define BB   16
#define FF   64
#define CC   1024          // B*F columns of x
#define EE   640000
#define ODIM 64
#define KDIM 192

// GEMM tile: 128 rows x 64 cols, 256 threads (8 warps = 4m x 2n)
#define BLK_M    128
#define AS_STRH  200        // halves per A row (192 + 8 pad) -> 400 B
#define BS_STRH  72         // halves per B row (64 + 8 pad)  -> 144 B
#define A_BUF_H  (BLK_M * AS_STRH)                      // halves per A buffer
#define GEMM_SMEM (A_BUF_H * 2 + KDIM * BS_STRH * 2)    // 78,848 B  (2 CTAs/SM)

// Scratch (allocation-free rule: __device__ globals) — fp16 x arrays
__device__ __half g_x0[NN * CC];
__device__ __half g_x1[NN * CC];
__device__ __half g_x2[NN * CC];
__device__ int    g_rp[NN + 1];

__device__ __forceinline__ uint32_t smem_u32(const void* p) {
    uint32_t a;
    asm("{ .reg .u64 t; cvta.to.shared.u64 t, %1; cvt.u32.u64 %0, t; }" : "=r"(a) : "l"(p));
    return a;
}

__device__ __forceinline__ void mma_f16(float* d, const uint32_t* a, const uint32_t* b) {
    asm volatile(
        "mma.sync.aligned.m16n8k16.row.col.f32.f16.f16.f32 "
        "{%0,%1,%2,%3}, {%4,%5,%6,%7}, {%8,%9}, {%0,%1,%2,%3};"
        : "+f"(d[0]), "+f"(d[1]), "+f"(d[2]), "+f"(d[3])
        : "r"(a[0]), "r"(a[1]), "r"(a[2]), "r"(a[3]), "r"(b[0]), "r"(b[1]));
}
__device__ __forceinline__ void ldm_x4(uint32_t* r, uint32_t addr) {
    asm volatile("ldmatrix.sync.aligned.m8n8.x4.shared.b16 {%0,%1,%2,%3}, [%4];"
                 : "=r"(r[0]), "=r"(r[1]), "=r"(r[2]), "=r"(r[3]) : "r"(addr));
}
__device__ __forceinline__ void ldm_x4_t(uint32_t* r, uint32_t addr) {
    asm volatile("ldmatrix.sync.aligned.m8n8.x4.trans.shared.b16 {%0,%1,%2,%3}, [%4];"
                 : "=r"(r[0]), "=r"(r[1]), "=r"(r[2]), "=r"(r[3]) : "r"(addr));
}
__device__ __forceinline__ void cp_async16(uint32_t dst, const void* src, int src_bytes) {
    asm volatile("cp.async.ca.shared.global [%0], [%1], 16, %2;"
                 :: "r"(dst), "l"(src), "r"(src_bytes));
}
#define CP_COMMIT() asm volatile("cp.async.commit_group;" ::: "memory")
#define CP_WAIT0()  asm volatile("cp.async.wait_group 0;" ::: "memory")

// ---------------------------------------------------------------------------
// 1) Pack inputs [B,N,F] fp32 -> x0 [N, B*F] fp16
// ---------------------------------------------------------------------------
__global__ void pack_kernel(const float4* __restrict__ in4) {
    int g  = blockIdx.x * 256 + threadIdx.x;   // 0 .. NN*128-1
    int f8 = g & 7;
    int b  = (g >> 3) & 15;
    int n  = g >> 7;
    float4 v0 = in4[(b * NN + n) * 16 + f8 * 2];
    float4 v1 = in4[(b * NN + n) * 16 + f8 * 2 + 1];
    __half2 h[4];
    h[0] = __float22half2_rn(make_float2(v0.x, v0.y));
    h[1] = __float22half2_rn(make_float2(v0.z, v0.w));
    h[2] = __float22half2_rn(make_float2(v1.x, v1.y));
    h[3] = __float22half2_rn(make_float2(v1.z, v1.w));
    ((uint4*)g_x0)[g] = *(uint4*)h;
}

// ---------------------------------------------------------------------------
// 2) Row pointers from sorted rows
// ---------------------------------------------------------------------------
__global__ void rowptr_kernel(const int* __restrict__ rows) {
    int i = blockIdx.x * 256 + threadIdx.x;
    if (i >= EE) return;
    int r    = rows[i];
    int prev = (i == 0) ? -1 : rows[i - 1];
    for (int rr = prev + 1; rr <= r; rr++) g_rp[rr] = i;
    if (i == EE - 1) {
        for (int rr = r + 1; rr <= NN; rr++) g_rp[rr] = EE;
    }
}

// ---------------------------------------------------------------------------
// 3) SpMM fp16: block (128 thr) per row; thread owns 8 half cols (1 uint4).
//    8-edge chunks, 8 gathers in flight, single 8-deep half2 chain per q,
//    flushed to fp32 once per chunk.
// ---------------------------------------------------------------------------
template <int PHASE>
__global__ void __launch_bounds__(128) spmm_kernel(const int* __restrict__ cols,
                                                   const float* __restrict__ vals) {
    const uint4* __restrict__ x = (const uint4*)(PHASE == 1 ? g_x0 : g_x1);
    uint4* __restrict__ y       = (uint4*)(PHASE == 1 ? g_x1 : g_x2);

    int n = blockIdx.x;
    int t = threadIdx.x;                 // uint4 column 0..127
    int s = g_rp[n];
    int e = g_rp[n + 1];

    __shared__ int sc[128];
    __shared__ __align__(16) __half2 svh[128];

    float acc[8];
    #pragma unroll
    for (int q = 0; q < 8; q++) acc[q] = 0.f;

    for (int base = s; base < e; base += 128) {
        int cnt = min(128, e - base);
        __syncthreads();
        if (t < cnt) {
            sc[t]  = cols[base + t];
            svh[t] = __float2half2_rn(vals[base + t]);
        }
        __syncthreads();

        int j = 0;
        for (; j + 8 <= cnt; j += 8) {
            int cidx[8];
            *(int4*)&cidx[0] = *(const int4*)&sc[j];
            *(int4*)&cidx[4] = *(const int4*)&sc[j + 4];
            __half2 v[8];
            *(uint4*)&v[0] = *(const uint4*)&svh[j];
            *(uint4*)&v[4] = *(const uint4*)&svh[j + 4];
            uint4 xv[8];
            #pragma unroll
            for (int ee = 0; ee < 8; ee++) xv[ee] = x[cidx[ee] * 128 + t];
            #pragma unroll
            for (int q = 0; q < 4; q++) {
                __half2 h = __hmul2(((const __half2*)&xv[0])[q], v[0]);
                #pragma unroll
                for (int ee = 1; ee < 8; ee++)
                    h = __hfma2(((const __half2*)&xv[ee])[q], v[ee], h);
                float2 f = __half22float2(h);
                acc[q * 2]     += f.x;
                acc[q * 2 + 1] += f.y;
            }
        }
        for (; j + 4 <= cnt; j += 4) {
            int4 c4 = *(const int4*)&sc[j];
            __half2 v[4];
            *(uint4*)&v[0] = *(const uint4*)&svh[j];
            uint4 xv[4];
            xv[0] = x[c4.x * 128 + t];
            xv[1] = x[c4.y * 128 + t];
            xv[2] = x[c4.z * 128 + t];
            xv[3] = x[c4.w * 128 + t];
            #pragma unroll
            for (int q = 0; q < 4; q++) {
                __half2 h = __hmul2(((const __half2*)&xv[0])[q], v[0]);
                h = __hfma2(((const __half2*)&xv[1])[q], v[1], h);
                h = __hfma2(((const __half2*)&xv[2])[q], v[2], h);
                h = __hfma2(((const __half2*)&xv[3])[q], v[3], h);
                float2 f = __half22float2(h);
                acc[q * 2]     += f.x;
                acc[q * 2 + 1] += f.y;
            }
        }
        for (; j < cnt; j++) {
            __half2 va = svh[j];
            uint4 xv = x[sc[j] * 128 + t];
            const __half2* h = (const __half2*)&xv;
            #pragma unroll
            for (int q = 0; q < 4; q++) {
                float2 f = __half22float2(__hmul2(h[q], va));
                acc[q * 2]     += f.x;
                acc[q * 2 + 1] += f.y;
            }
        }
    }

    if (PHASE == 2) {
        uint4 x0v = ((const uint4*)g_x0)[n * 128 + t];
        const __half2* h = (const __half2*)&x0v;
        #pragma unroll
        for (int q = 0; q < 4; q++) {
            float2 f = __half22float2(h[q]);
            acc[q * 2]     = 2.f * acc[q * 2]     - f.x;
            acc[q * 2 + 1] = 2.f * acc[q * 2 + 1] - f.y;
        }
    }

    __half2 hr[4];
    #pragma unroll
    for (int q = 0; q < 4; q++)
        hr[q] = __float22half2_rn(make_float2(acc[q * 2], acc[q * 2 + 1]));
    y[n * 128 + t] = *(uint4*)hr;
}

// ---------------------------------------------------------------------------
// 4) GEMM fp16 mma m16n8k16 + ldmatrix. Single A buffer, 2 CTAs/SM
//    (cross-CTA overlap of staging vs compute). B staged once; 4-batch loop.
// ---------------------------------------------------------------------------
__device__ __forceinline__ void prefetch_A(uint32_t As_dst, int n0, int b, int t) {
    const __half* __restrict__ xs0 = g_x0;
    const __half* __restrict__ xs1 = g_x1;
    const __half* __restrict__ xs2 = g_x2;
    for (int idx = t; idx < BLK_M * 24; idx += 256) {
        int q  = idx & 7;
        int m  = (idx >> 3) % 3;
        int nl = idx / 24;
        int n  = n0 + nl;
        const __half* src = (m == 0 ? xs0 : (m == 1 ? xs1 : xs2));
        int nc = n < NN ? n : 0;
        uint32_t dst = As_dst + (uint32_t)(nl * AS_STRH + m * 64 + q * 8) * 2;
        cp_async16(dst, src + (size_t)nc * CC + b * 64 + q * 8, n < NN ? 16 : 0);
    }
    CP_COMMIT();
}

__global__ void __launch_bounds__(256, 2) gemm_mma_kernel(const float* __restrict__ weight,
                                                          const float* __restrict__ bias,
                                                          float* __restrict__ out) {
    extern __shared__ char sh[];
    __half* Bs = (__half*)(sh + A_BUF_H * 2);         // [192][72] halves

    int t   = threadIdx.x;
    int wid = t >> 5;
    int lid = t & 31;
    int n0  = blockIdx.x * BLK_M;
    int b0  = blockIdx.y * 4;

    uint32_t As_base = smem_u32(sh);
    uint32_t Bs_base = smem_u32(Bs);

    // Prefetch A(b0)
    prefetch_A(As_base, n0, b0, t);

    // Stage B once: weight[(f*3+m)][o] fp32 -> Bs[k=m*64+f][o] fp16
    for (int idx = t; idx < KDIM * 16; idx += 256) {
        int krow = idx >> 4;
        int o4   = idx & 15;
        int f    = krow & 63;
        int m    = krow >> 6;
        float4 w = ((const float4*)weight)[(f * 3 + m) * 16 + o4];
        __half2 h2[2];
        h2[0] = __float22half2_rn(make_float2(w.x, w.y));
        h2[1] = __float22half2_rn(make_float2(w.z, w.w));
        *(uint2*)(Bs + krow * BS_STRH + o4 * 4) = *(uint2*)h2;
    }

    int wm = wid & 3;                    // 4 m-warps
    int wn = wid >> 2;                   // 2 n-warps
    int grp = lid >> 2;                  // 0..7
    int tig = lid & 3;                   // 0..3
    int tl = lid >> 3;                   // ldmatrix tile 0..3
    int lr = (lid & 7) + (tl & 1) * 8;   // row within 16
    int lk = (tl >> 1) * 8;              // half-col offset within 16

    for (int bi = 0; bi < 4; bi++) {
        int b = b0 + bi;

        CP_WAIT0();
        __syncthreads();

        float d[2][4][4];
        #pragma unroll
        for (int i = 0; i < 2; i++)
            #pragma unroll
            for (int j = 0; j < 4; j++)
                #pragma unroll
                for (int q = 0; q < 4; q++) d[i][j][q] = 0.f;

        #pragma unroll 4
        for (int ks = 0; ks < 12; ks++) {
            int k0 = ks * 16;
            uint32_t a[2][4], bq[2][4];
            #pragma unroll
            for (int i = 0; i < 2; i++) {
                uint32_t addr = As_base + (uint32_t)((wm * 32 + i * 16 + lr) * (AS_STRH * 2)
                                                     + (k0 + lk) * 2);
                ldm_x4(a[i], addr);
            }
            #pragma unroll
            for (int jj = 0; jj < 2; jj++) {
                uint32_t addr = Bs_base + (uint32_t)((k0 + lr) * (BS_STRH * 2)
                                                     + (wn * 32 + jj * 16 + lk) * 2);
                ldm_x4_t(bq[jj], addr);
            }
            #pragma unroll
            for (int i = 0; i < 2; i++) {
                #pragma unroll
                for (int j = 0; j < 4; j++) {
                    uint32_t bb[2] = { bq[j >> 1][(j & 1) * 2], bq[j >> 1][(j & 1) * 2 + 1] };
                    mma_f16(d[i][j], a[i], bb);
                }
            }
        }

        __syncthreads();                 // A consumed; safe to restage
        if (bi < 3) prefetch_A(As_base, n0, b + 1, t);

        // Epilogue (overlaps next A prefetch)
        #pragma unroll
        for (int i = 0; i < 2; i++) {
            #pragma unroll
            for (int j = 0; j < 4; j++) {
                int cc = wn * 32 + j * 8 + 2 * tig;
                float2 bb = *(const float2*)(bias + cc);
                int rn = n0 + wm * 32 + i * 16 + grp;
                if (rn < NN) {
                    float2 v = make_float2(d[i][j][0] + bb.x, d[i][j][1] + bb.y);
                    *(float2*)(out + ((long long)b * NN + rn) * ODIM + cc) = v;
                }
                int rn2 = rn + 8;
                if (rn2 < NN) {
                    float2 v = make_float2(d[i][j][2] + bb.x, d[i][j][3] + bb.y);
                    *(float2*)(out + ((long long)b * NN + rn2) * ODIM + cc) = v;
                }
            }
        }
    }
}

// ---------------------------------------------------------------------------
// Launch
// ---------------------------------------------------------------------------
extern "C" void kernel_launch(void* const* d_in, const int* in_sizes, int n_in,
                              void* d_out, int out_size) {
    const float4* inputs = (const float4*)d_in[0];
    const int*    rows   = (const int*)d_in[1];
    const int*    cols   = (const int*)d_in[2];
    const float*  vals   = (const float*)d_in[3];
    const float*  weight = (const float*)d_in[4];
    const float*  bias   = (const float*)d_in[5];
    float*        out    = (float*)d_out;

    cudaFuncSetAttribute(gemm_mma_kernel, cudaFuncAttributeMaxDynamicSharedMemorySize,
                         GEMM_SMEM);

    pack_kernel<<<NN * 128 / 256, 256>>>(inputs);
    rowptr_kernel<<<(EE + 255) / 256, 256>>>(rows);
    spmm_kernel<1><<<NN, 128>>>(cols, vals);
    spmm_kernel<2><<<NN, 128>>>(cols, vals);
    gemm_mma_kernel<<<dim3((NN + BLK_M - 1) / BLK_M, 4), 256, GEMM_SMEM>>>(weight, bias, out);
}

// round 14
// speedup vs baseline: 5.2917x; 1.0340x over previous
#include <cuda_runtime.h>
#include <cuda_fp16.h>
#include <cstdint>

// Problem constants
#define NN   20000
#define BB   16
#define FF   64
#define CC   1024          // B*F columns of x
#define EE   640000
#define ODIM 64
#define KDIM 192

// GEMM tile: 128 rows x 64 cols, 256 threads (8 warps = 4m x 2n)
#define BLK_M    128
#define AS_STRH  200        // halves per A row (192 + 8 pad) -> 400 B
#define BS_STRH  72         // halves per B row (64 + 8 pad)  -> 144 B
#define A_BUF_H  (BLK_M * AS_STRH)                      // halves per A buffer
#define GEMM_SMEM (A_BUF_H * 2 + KDIM * BS_STRH * 2)    // 78,848 B  (2 CTAs/SM)

// Scratch (allocation-free rule: __device__ globals) — fp16 x arrays
__device__ __half g_x0[NN * CC];
__device__ __half g_x1[NN * CC];
__device__ __half g_x2[NN * CC];
__device__ int    g_rp[NN + 1];

__device__ __forceinline__ uint32_t smem_u32(const void* p) {
    uint32_t a;
    asm("{ .reg .u64 t; cvta.to.shared.u64 t, %1; cvt.u32.u64 %0, t; }" : "=r"(a) : "l"(p));
    return a;
}

__device__ __forceinline__ void mma_f16(float* d, const uint32_t* a, const uint32_t* b) {
    asm volatile(
        "mma.sync.aligned.m16n8k16.row.col.f32.f16.f16.f32 "
        "{%0,%1,%2,%3}, {%4,%5,%6,%7}, {%8,%9}, {%0,%1,%2,%3};"
        : "+f"(d[0]), "+f"(d[1]), "+f"(d[2]), "+f"(d[3])
        : "r"(a[0]), "r"(a[1]), "r"(a[2]), "r"(a[3]), "r"(b[0]), "r"(b[1]));
}
__device__ __forceinline__ void ldm_x4(uint32_t* r, uint32_t addr) {
    asm volatile("ldmatrix.sync.aligned.m8n8.x4.shared.b16 {%0,%1,%2,%3}, [%4];"
                 : "=r"(r[0]), "=r"(r[1]), "=r"(r[2]), "=r"(r[3]) : "r"(addr));
}
__device__ __forceinline__ void ldm_x4_t(uint32_t* r, uint32_t addr) {
    asm volatile("ldmatrix.sync.aligned.m8n8.x4.trans.shared.b16 {%0,%1,%2,%3}, [%4];"
                 : "=r"(r[0]), "=r"(r[1]), "=r"(r[2]), "=r"(r[3]) : "r"(addr));
}
__device__ __forceinline__ void cp_async16(uint32_t dst, const void* src, int src_bytes) {
    asm volatile("cp.async.ca.shared.global [%0], [%1], 16, %2;"
                 :: "r"(dst), "l"(src), "r"(src_bytes));
}
#define CP_COMMIT() asm volatile("cp.async.commit_group;" ::: "memory")
#define CP_WAIT0()  asm volatile("cp.async.wait_group 0;" ::: "memory")

// ---------------------------------------------------------------------------
// 1) Prelude: blocks [0,10000) pack inputs [B,N,F] fp32 -> x0 [N,B*F] fp16;
//    blocks [10000,12500) build row pointers from sorted rows.
// ---------------------------------------------------------------------------
#define PACK_BLOCKS   (NN * 128 / 256)        // 10000
#define RP_BLOCKS     ((EE + 255) / 256)      // 2500

__global__ void prelude_kernel(const float4* __restrict__ in4,
                               const int* __restrict__ rows) {
    if (blockIdx.x < PACK_BLOCKS) {
        int g  = blockIdx.x * 256 + threadIdx.x;   // 0 .. NN*128-1
        int f8 = g & 7;
        int b  = (g >> 3) & 15;
        int n  = g >> 7;
        float4 v0 = in4[(b * NN + n) * 16 + f8 * 2];
        float4 v1 = in4[(b * NN + n) * 16 + f8 * 2 + 1];
        __half2 h[4];
        h[0] = __float22half2_rn(make_float2(v0.x, v0.y));
        h[1] = __float22half2_rn(make_float2(v0.z, v0.w));
        h[2] = __float22half2_rn(make_float2(v1.x, v1.y));
        h[3] = __float22half2_rn(make_float2(v1.z, v1.w));
        ((uint4*)g_x0)[g] = *(uint4*)h;
    } else {
        int i = (blockIdx.x - PACK_BLOCKS) * 256 + threadIdx.x;
        if (i >= EE) return;
        int r    = rows[i];
        int prev = (i == 0) ? -1 : rows[i - 1];
        for (int rr = prev + 1; rr <= r; rr++) g_rp[rr] = i;
        if (i == EE - 1) {
            for (int rr = r + 1; rr <= NN; rr++) g_rp[rr] = EE;
        }
    }
}

// ---------------------------------------------------------------------------
// 2) SpMM fp16: block (128 thr) per row; thread owns 8 half cols (1 uint4).
//    8-edge chunks, 8 gathers in flight, single 8-deep half2 chain per q.
//    PHASE 2 uses streaming hints: y store (__stcs) and x0 read (__ldcs)
//    never re-used here -> keep L2 for the x1 gather working set.
// ---------------------------------------------------------------------------
template <int PHASE>
__global__ void __launch_bounds__(128) spmm_kernel(const int* __restrict__ cols,
                                                   const float* __restrict__ vals) {
    const uint4* __restrict__ x = (const uint4*)(PHASE == 1 ? g_x0 : g_x1);
    uint4* __restrict__ y       = (uint4*)(PHASE == 1 ? g_x1 : g_x2);

    int n = blockIdx.x;
    int t = threadIdx.x;                 // uint4 column 0..127
    int s = g_rp[n];
    int e = g_rp[n + 1];

    __shared__ int sc[128];
    __shared__ __align__(16) __half2 svh[128];

    float acc[8];
    #pragma unroll
    for (int q = 0; q < 8; q++) acc[q] = 0.f;

    for (int base = s; base < e; base += 128) {
        int cnt = min(128, e - base);
        __syncthreads();
        if (t < cnt) {
            sc[t]  = cols[base + t];
            svh[t] = __float2half2_rn(vals[base + t]);
        }
        __syncthreads();

        int j = 0;
        for (; j + 8 <= cnt; j += 8) {
            int cidx[8];
            *(int4*)&cidx[0] = *(const int4*)&sc[j];
            *(int4*)&cidx[4] = *(const int4*)&sc[j + 4];
            __half2 v[8];
            *(uint4*)&v[0] = *(const uint4*)&svh[j];
            *(uint4*)&v[4] = *(const uint4*)&svh[j + 4];
            uint4 xv[8];
            #pragma unroll
            for (int ee = 0; ee < 8; ee++) xv[ee] = x[cidx[ee] * 128 + t];
            #pragma unroll
            for (int q = 0; q < 4; q++) {
                __half2 h = __hmul2(((const __half2*)&xv[0])[q], v[0]);
                #pragma unroll
                for (int ee = 1; ee < 8; ee++)
                    h = __hfma2(((const __half2*)&xv[ee])[q], v[ee], h);
                float2 f = __half22float2(h);
                acc[q * 2]     += f.x;
                acc[q * 2 + 1] += f.y;
            }
        }
        for (; j + 4 <= cnt; j += 4) {
            int4 c4 = *(const int4*)&sc[j];
            __half2 v[4];
            *(uint4*)&v[0] = *(const uint4*)&svh[j];
            uint4 xv[4];
            xv[0] = x[c4.x * 128 + t];
            xv[1] = x[c4.y * 128 + t];
            xv[2] = x[c4.z * 128 + t];
            xv[3] = x[c4.w * 128 + t];
            #pragma unroll
            for (int q = 0; q < 4; q++) {
                __half2 h = __hmul2(((const __half2*)&xv[0])[q], v[0]);
                h = __hfma2(((const __half2*)&xv[1])[q], v[1], h);
                h = __hfma2(((const __half2*)&xv[2])[q], v[2], h);
                h = __hfma2(((const __half2*)&xv[3])[q], v[3], h);
                float2 f = __half22float2(h);
                acc[q * 2]     += f.x;
                acc[q * 2 + 1] += f.y;
            }
        }
        for (; j < cnt; j++) {
            __half2 va = svh[j];
            uint4 xv = x[sc[j] * 128 + t];
            const __half2* h = (const __half2*)&xv;
            #pragma unroll
            for (int q = 0; q < 4; q++) {
                float2 f = __half22float2(__hmul2(h[q], va));
                acc[q * 2]     += f.x;
                acc[q * 2 + 1] += f.y;
            }
        }
    }

    if (PHASE == 2) {
        uint4 x0v = __ldcs(((const uint4*)g_x0) + n * 128 + t);
        const __half2* h = (const __half2*)&x0v;
        #pragma unroll
        for (int q = 0; q < 4; q++) {
            float2 f = __half22float2(h[q]);
            acc[q * 2]     = 2.f * acc[q * 2]     - f.x;
            acc[q * 2 + 1] = 2.f * acc[q * 2 + 1] - f.y;
        }
    }

    __half2 hr[4];
    #pragma unroll
    for (int q = 0; q < 4; q++)
        hr[q] = __float22half2_rn(make_float2(acc[q * 2], acc[q * 2 + 1]));
    if (PHASE == 2) {
        __stcs(y + n * 128 + t, *(uint4*)hr);    // streamed: read later only by GEMM
    } else {
        y[n * 128 + t] = *(uint4*)hr;            // x1: next gather target, keep in L2
    }
}

// ---------------------------------------------------------------------------
// 3) GEMM fp16 mma m16n8k16 + ldmatrix. Single A buffer, 2 CTAs/SM.
//    B staged once; 4-batch loop; out stores streamed (__stcs).
// ---------------------------------------------------------------------------
__device__ __forceinline__ void prefetch_A(uint32_t As_dst, int n0, int b, int t) {
    const __half* __restrict__ xs0 = g_x0;
    const __half* __restrict__ xs1 = g_x1;
    const __half* __restrict__ xs2 = g_x2;
    for (int idx = t; idx < BLK_M * 24; idx += 256) {
        int q  = idx & 7;
        int m  = (idx >> 3) % 3;
        int nl = idx / 24;
        int n  = n0 + nl;
        const __half* src = (m == 0 ? xs0 : (m == 1 ? xs1 : xs2));
        int nc = n < NN ? n : 0;
        uint32_t dst = As_dst + (uint32_t)(nl * AS_STRH + m * 64 + q * 8) * 2;
        cp_async16(dst, src + (size_t)nc * CC + b * 64 + q * 8, n < NN ? 16 : 0);
    }
    CP_COMMIT();
}

__global__ void __launch_bounds__(256, 2) gemm_mma_kernel(const float* __restrict__ weight,
                                                          const float* __restrict__ bias,
                                                          float* __restrict__ out) {
    extern __shared__ char sh[];
    __half* Bs = (__half*)(sh + A_BUF_H * 2);         // [192][72] halves

    int t   = threadIdx.x;
    int wid = t >> 5;
    int lid = t & 31;
    int n0  = blockIdx.x * BLK_M;
    int b0  = blockIdx.y * 4;

    uint32_t As_base = smem_u32(sh);
    uint32_t Bs_base = smem_u32(Bs);

    // Prefetch A(b0)
    prefetch_A(As_base, n0, b0, t);

    // Stage B once: weight[(f*3+m)][o] fp32 -> Bs[k=m*64+f][o] fp16
    for (int idx = t; idx < KDIM * 16; idx += 256) {
        int krow = idx >> 4;
        int o4   = idx & 15;
        int f    = krow & 63;
        int m    = krow >> 6;
        float4 w = ((const float4*)weight)[(f * 3 + m) * 16 + o4];
        __half2 h2[2];
        h2[0] = __float22half2_rn(make_float2(w.x, w.y));
        h2[1] = __float22half2_rn(make_float2(w.z, w.w));
        *(uint2*)(Bs + krow * BS_STRH + o4 * 4) = *(uint2*)h2;
    }

    int wm = wid & 3;                    // 4 m-warps
    int wn = wid >> 2;                   // 2 n-warps
    int grp = lid >> 2;                  // 0..7
    int tig = lid & 3;                   // 0..3
    int tl = lid >> 3;                   // ldmatrix tile 0..3
    int lr = (lid & 7) + (tl & 1) * 8;   // row within 16
    int lk = (tl >> 1) * 8;              // half-col offset within 16

    for (int bi = 0; bi < 4; bi++) {
        int b = b0 + bi;

        CP_WAIT0();
        __syncthreads();

        float d[2][4][4];
        #pragma unroll
        for (int i = 0; i < 2; i++)
            #pragma unroll
            for (int j = 0; j < 4; j++)
                #pragma unroll
                for (int q = 0; q < 4; q++) d[i][j][q] = 0.f;

        #pragma unroll 4
        for (int ks = 0; ks < 12; ks++) {
            int k0 = ks * 16;
            uint32_t a[2][4], bq[2][4];
            #pragma unroll
            for (int i = 0; i < 2; i++) {
                uint32_t addr = As_base + (uint32_t)((wm * 32 + i * 16 + lr) * (AS_STRH * 2)
                                                     + (k0 + lk) * 2);
                ldm_x4(a[i], addr);
            }
            #pragma unroll
            for (int jj = 0; jj < 2; jj++) {
                uint32_t addr = Bs_base + (uint32_t)((k0 + lr) * (BS_STRH * 2)
                                                     + (wn * 32 + jj * 16 + lk) * 2);
                ldm_x4_t(bq[jj], addr);
            }
            #pragma unroll
            for (int i = 0; i < 2; i++) {
                #pragma unroll
                for (int j = 0; j < 4; j++) {
                    uint32_t bb[2] = { bq[j >> 1][(j & 1) * 2], bq[j >> 1][(j & 1) * 2 + 1] };
                    mma_f16(d[i][j], a[i], bb);
                }
            }
        }

        __syncthreads();                 // A consumed; safe to restage
        if (bi < 3) prefetch_A(As_base, n0, b + 1, t);

        // Epilogue (overlaps next A prefetch); streamed stores
        #pragma unroll
        for (int i = 0; i < 2; i++) {
            #pragma unroll
            for (int j = 0; j < 4; j++) {
                int cc = wn * 32 + j * 8 + 2 * tig;
                float2 bb = *(const float2*)(bias + cc);
                int rn = n0 + wm * 32 + i * 16 + grp;
                if (rn < NN) {
                    float2 v = make_float2(d[i][j][0] + bb.x, d[i][j][1] + bb.y);
                    __stcs((float2*)(out + ((long long)b * NN + rn) * ODIM + cc), v);
                }
                int rn2 = rn + 8;
                if (rn2 < NN) {
                    float2 v = make_float2(d[i][j][2] + bb.x, d[i][j][3] + bb.y);
                    __stcs((float2*)(out + ((long long)b * NN + rn2) * ODIM + cc), v);
                }
            }
        }
    }
}

// ---------------------------------------------------------------------------
// Launch
// ---------------------------------------------------------------------------
extern "C" void kernel_launch(void* const* d_in, const int* in_sizes, int n_in,
                              void* d_out, int out_size) {
    const float4* inputs = (const float4*)d_in[0];
    const int*    rows   = (const int*)d_in[1];
    const int*    cols   = (const int*)d_in[2];
    const float*  vals   = (const float*)d_in[3];
    const float*  weight = (const float*)d_in[4];
    const float*  bias   = (const float*)d_in[5];
    float*        out    = (float*)d_out;

    cudaFuncSetAttribute(gemm_mma_kernel, cudaFuncAttributeMaxDynamicSharedMemorySize,
                         GEMM_SMEM);

    prelude_kernel<<<PACK_BLOCKS + RP_BLOCKS, 256>>>(inputs, rows);
    spmm_kernel<1><<<NN, 128>>>(cols, vals);
    spmm_kernel<2><<<NN, 128>>>(cols, vals);
    gemm_mma_kernel<<<dim3((NN + BLK_M - 1) / BLK_M, 4), 256, GEMM_SMEM>>>(weight, bias, out);
}